// round 1
// baseline (speedup 1.0000x reference)
#include <cuda_runtime.h>
#include <math.h>

// Problem constants
#define BATCH   2
#define SEQ     2048
#define DMODEL  1024
#define NHEADS  16
#define DK      64
#define MTOT    (BATCH * SEQ)        // 4096 rows for all GEMMs
#define SCALE   0.125f               // 1/sqrt(64)

// Scratch (allocation-free rule: __device__ globals)
__device__ float g_q[MTOT * DMODEL];
__device__ float g_k[MTOT * DMODEL];
__device__ float g_v[MTOT * DMODEL];
__device__ float g_o[MTOT * DMODEL];

// ---------------------------------------------------------------------------
// GEMM (NT): C[m,n] = sum_k A[m,k] * B[n,k]
// A: [M,K] row-major, B: [N,K] row-major (both K-contiguous), C: [M,N].
// M=4096, N=1024, K=1024 fixed. 128x128 tile, BK=16, 256 threads, 8x8/thread.
// ---------------------------------------------------------------------------
__global__ __launch_bounds__(256) void gemm_nt_kernel(
    const float* __restrict__ A, const float* __restrict__ B,
    float* __restrict__ C)
{
    const int N = DMODEL, K = DMODEL;
    __shared__ float As[16][132];   // [k][m], padded to soften store conflicts
    __shared__ float Bs[16][132];   // [k][n]

    const int tid = threadIdx.x;
    const int tx  = tid & 15;       // n-tile subcol
    const int ty  = tid >> 4;       // m-tile subrow
    const int bm  = blockIdx.y * 128;
    const int bn  = blockIdx.x * 128;

    float acc[8][8];
#pragma unroll
    for (int i = 0; i < 8; i++)
#pragma unroll
        for (int j = 0; j < 8; j++) acc[i][j] = 0.f;

    for (int k0 = 0; k0 < K; k0 += 16) {
#pragma unroll
        for (int l = 0; l < 2; l++) {
            int f  = tid + l * 256;      // 0..511 float4 slots
            int r  = f >> 2;             // 0..127 tile row
            int cg = (f & 3) << 2;       // 0,4,8,12 k-subcol
            float4 av = *(const float4*)(A + (size_t)(bm + r) * K + k0 + cg);
            As[cg + 0][r] = av.x; As[cg + 1][r] = av.y;
            As[cg + 2][r] = av.z; As[cg + 3][r] = av.w;
            float4 bv = *(const float4*)(B + (size_t)(bn + r) * K + k0 + cg);
            Bs[cg + 0][r] = bv.x; Bs[cg + 1][r] = bv.y;
            Bs[cg + 2][r] = bv.z; Bs[cg + 3][r] = bv.w;
        }
        __syncthreads();
#pragma unroll
        for (int k = 0; k < 16; k++) {
            float ar[8], br[8];
            *(float4*)&ar[0] = *(const float4*)&As[k][ty * 8];
            *(float4*)&ar[4] = *(const float4*)&As[k][ty * 8 + 4];
            *(float4*)&br[0] = *(const float4*)&Bs[k][tx * 8];
            *(float4*)&br[4] = *(const float4*)&Bs[k][tx * 8 + 4];
#pragma unroll
            for (int i = 0; i < 8; i++)
#pragma unroll
                for (int j = 0; j < 8; j++)
                    acc[i][j] = fmaf(ar[i], br[j], acc[i][j]);
        }
        __syncthreads();
    }

#pragma unroll
    for (int i = 0; i < 8; i++) {
        size_t off = (size_t)(bm + ty * 8 + i) * N + bn + tx * 8;
        float4 v0 = make_float4(acc[i][0], acc[i][1], acc[i][2], acc[i][3]);
        float4 v1 = make_float4(acc[i][4], acc[i][5], acc[i][6], acc[i][7]);
        *(float4*)(C + off)     = v0;
        *(float4*)(C + off + 4) = v1;
    }
}

// ---------------------------------------------------------------------------
// RoPE (in place). One thread per (b,s,head,freq) pair.
// inv_freq via fp64 exp2; angle rounded to fp32 (matches reference), trig in
// fp64 (safe vs --use_fast_math and large angles up to ~2047 rad).
// ---------------------------------------------------------------------------
__global__ void rope_kernel(float* __restrict__ t, const int* __restrict__ pos)
{
    const int NP = BATCH * SEQ * (DMODEL / 2);
    int p = blockIdx.x * blockDim.x + threadIdx.x;
    if (p >= NP) return;

    int sf     = p >> 9;           // flat (b*SEQ + s), 512 pairs per token
    int within = p & 511;
    int i      = within & 31;      // frequency index (dk/2 = 32)
    int h      = within >> 5;
    int s      = sf & (SEQ - 1);

    // inv_freq[i] = 10000^(-2i/64) = exp2(-i * log2(10000)/32)
    float invf = (float)exp2(-(double)i * 0.4152410118609190);
    float ang  = (float)pos[s] * invf;   // fp32 rounding as in reference
    double sd, cd;
    sincos((double)ang, &sd, &cd);
    float c = (float)cd, sn = (float)sd;

    float2* pp = (float2*)(t + (size_t)sf * DMODEL + h * DK + 2 * i);
    float2 v = *pp;
    float2 o;
    o.x = v.x * c - v.y * sn;
    o.y = v.y * c + v.x * sn;
    *pp = o;
}

// ---------------------------------------------------------------------------
// Causal flash attention, fp32, online softmax.
// Grid: (SEQ/64, NHEADS, BATCH). 128 threads: 2 threads per query row,
// each owns 32 of the 64 dk dims. 64-key tiles staged in shared.
// ---------------------------------------------------------------------------
__global__ __launch_bounds__(128) void attn_kernel(
    const float* __restrict__ Q, const float* __restrict__ K,
    const float* __restrict__ V, float* __restrict__ O)
{
    __shared__ float Ks[64][64];
    __shared__ float Vs[64][64];

    const int t    = threadIdx.x;
    const int row  = t >> 1;
    const int cb   = (t & 1) * 32;       // column base within dk
    const int b    = blockIdx.z;
    const int h    = blockIdx.y;
    const int q0   = blockIdx.x * 64;
    const int qidx = q0 + row;

    const size_t base_bh = (size_t)b * SEQ * DMODEL + (size_t)h * DK;

    float qreg[32];
    {
        const float* qp = Q + base_bh + (size_t)qidx * DMODEL + cb;
#pragma unroll
        for (int j = 0; j < 32; j += 4)
            *(float4*)&qreg[j] = *(const float4*)(qp + j);
    }

    float m_i = -INFINITY, l_i = 0.f;
    float acc[32];
#pragma unroll
    for (int j = 0; j < 32; j++) acc[j] = 0.f;

    const int ktiles = (q0 >> 6) + 1;     // causal: tiles 0..q0/64 inclusive
    for (int kt = 0; kt < ktiles; kt++) {
        const float* kp = K + base_bh + (size_t)(kt * 64 + row) * DMODEL + cb;
        const float* vp = V + base_bh + (size_t)(kt * 64 + row) * DMODEL + cb;
#pragma unroll
        for (int j = 0; j < 32; j += 4) {
            *(float4*)&Ks[row][cb + j] = *(const float4*)(kp + j);
            *(float4*)&Vs[row][cb + j] = *(const float4*)(vp + j);
        }
        __syncthreads();

#pragma unroll 4
        for (int kc = 0; kc < 64; kc++) {
            int key = kt * 64 + kc;
            float partial = 0.f;
#pragma unroll
            for (int j = 0; j < 32; j++)
                partial = fmaf(qreg[j], Ks[kc][cb + j], partial);
            partial += __shfl_xor_sync(0xffffffffu, partial, 1);

            float s = (key <= qidx) ? partial * SCALE : -INFINITY;
            float m_new = fmaxf(m_i, s);
            float corr  = expf(m_i - m_new);   // 0 on first finite score
            float pexp  = expf(s - m_new);     // 0 for masked keys
            l_i = l_i * corr + pexp;
#pragma unroll
            for (int j = 0; j < 32; j++)
                acc[j] = fmaf(acc[j], corr, pexp * Vs[kc][cb + j]);
            m_i = m_new;
        }
        __syncthreads();
    }

    const float inv = 1.f / l_i;
    float* op = O + base_bh + (size_t)qidx * DMODEL + cb;
#pragma unroll
    for (int j = 0; j < 32; j += 4) {
        float4 o4 = make_float4(acc[j] * inv, acc[j + 1] * inv,
                                acc[j + 2] * inv, acc[j + 3] * inv);
        *(float4*)(op + j) = o4;
    }
}

// ---------------------------------------------------------------------------
// Launch
// ---------------------------------------------------------------------------
extern "C" void kernel_launch(void* const* d_in, const int* in_sizes, int n_in,
                              void* d_out, int out_size)
{
    const float* x  = (const float*)d_in[0];
    const float* Wq = (const float*)d_in[1];
    const float* Wk = (const float*)d_in[2];
    const float* Wv = (const float*)d_in[3];
    const float* Wo = (const float*)d_in[4];
    const int*   tp = (const int*)d_in[5];
    float* out = (float*)d_out;

    float *q, *k, *v, *o;
    cudaGetSymbolAddress((void**)&q, g_q);
    cudaGetSymbolAddress((void**)&k, g_k);
    cudaGetSymbolAddress((void**)&v, g_v);
    cudaGetSymbolAddress((void**)&o, g_o);

    dim3 ggrid(DMODEL / 128, MTOT / 128);   // (8, 32)
    gemm_nt_kernel<<<ggrid, 256>>>(x, Wq, q);
    gemm_nt_kernel<<<ggrid, 256>>>(x, Wk, k);
    gemm_nt_kernel<<<ggrid, 256>>>(x, Wv, v);

    const int NP = BATCH * SEQ * (DMODEL / 2);
    rope_kernel<<<(NP + 255) / 256, 256>>>(q, tp);
    rope_kernel<<<(NP + 255) / 256, 256>>>(k, tp);

    attn_kernel<<<dim3(SEQ / 64, NHEADS, BATCH), 128>>>(q, k, v, o);

    gemm_nt_kernel<<<ggrid, 256>>>(o, Wo, out);
}

// round 4
// speedup vs baseline: 1.4120x; 1.4120x over previous
#include <cuda_runtime.h>
#include <cuda_bf16.h>
#include <math.h>
#include <stdint.h>

// ---------------------------------------------------------------------------
// Problem constants
// ---------------------------------------------------------------------------
#define BATCH   2
#define SEQ     2048
#define DMODEL  1024
#define NHEADS  16
#define DK      64
#define MTOT    (BATCH * SEQ)        // 4096
#define SCALE   0.125f               // 1/sqrt(64)

// ---------------------------------------------------------------------------
// Scratch (__device__ globals; allocation-free rule)
// ---------------------------------------------------------------------------
__device__ float g_q[MTOT * DMODEL];
__device__ float g_k[MTOT * DMODEL];
__device__ float g_v[MTOT * DMODEL];
__device__ float g_o[MTOT * DMODEL];
__device__ __nv_bfloat16 g_ahi[MTOT * DMODEL];
__device__ __nv_bfloat16 g_alo[MTOT * DMODEL];
__device__ __nv_bfloat16 g_whi[DMODEL * DMODEL];
__device__ __nv_bfloat16 g_wlo[DMODEL * DMODEL];
__device__ float2 g_cs[SEQ * (DK / 2)];

// ---------------------------------------------------------------------------
// PTX helpers (portable sm_80+ tensor-core path; tcgen05 is rejected by this
// toolchain's compute_103 virtual target)
// ---------------------------------------------------------------------------
__device__ __forceinline__ uint32_t smem_to_u32(const void* p) {
    uint32_t a;
    asm("{ .reg .u64 t; cvta.to.shared.u64 t, %1; cvt.u32.u64 %0, t; }"
        : "=r"(a) : "l"(p));
    return a;
}

__device__ __forceinline__ void cp_async16(uint32_t dst, const void* src) {
    asm volatile("cp.async.cg.shared.global [%0], [%1], 16;" :: "r"(dst), "l"(src));
}

__device__ __forceinline__ void ldsm4(uint32_t* r, uint32_t addr) {
    asm volatile("ldmatrix.sync.aligned.m8n8.x4.shared.b16 {%0,%1,%2,%3}, [%4];"
                 : "=r"(r[0]), "=r"(r[1]), "=r"(r[2]), "=r"(r[3]) : "r"(addr));
}

__device__ __forceinline__ void ldsm2(uint32_t* r, uint32_t addr) {
    asm volatile("ldmatrix.sync.aligned.m8n8.x2.shared.b16 {%0,%1}, [%2];"
                 : "=r"(r[0]), "=r"(r[1]) : "r"(addr));
}

__device__ __forceinline__ void mma_bf16(float* d, const uint32_t* a, const uint32_t* b) {
    asm volatile(
        "mma.sync.aligned.m16n8k16.row.col.f32.bf16.bf16.f32 "
        "{%0,%1,%2,%3}, {%4,%5,%6,%7}, {%8,%9}, {%0,%1,%2,%3};"
        : "+f"(d[0]), "+f"(d[1]), "+f"(d[2]), "+f"(d[3])
        : "r"(a[0]), "r"(a[1]), "r"(a[2]), "r"(a[3]), "r"(b[0]), "r"(b[1]));
}

// ---------------------------------------------------------------------------
// GEMM (NT) via mma.sync bf16x3: C[m,n] = sum_k A[m,k]*B[n,k], fp32-equivalent.
// A -> (Ahi, Alo), B -> (Bhi, Blo);  C = AhiBhi + AhiBlo + AloBhi (fp32 accum).
// M=4096, N=1024, K=1024. CTA tile 128x128, BK=32, 2-stage cp.async pipeline.
// 8 warps: warp tile 64x32 (mwarp = wid&1, nwarp = wid>>2? no: wid>>1).
// SMEM row stride padded to 40 bf16 (80B) -> conflict-free ldmatrix.
// ---------------------------------------------------------------------------
#define TILE_B  10240u               // 128 rows * 40 bf16 * 2B
#define STAGE_B 40960u               // 4 matrices (Ahi,Alo,Bhi,Blo)
#define GEMM_SMEM (2 * STAGE_B)      // 81920 B dynamic

__global__ __launch_bounds__(256) void gemm_mma(
    const __nv_bfloat16* __restrict__ Ahi, const __nv_bfloat16* __restrict__ Alo,
    const __nv_bfloat16* __restrict__ Bhi, const __nv_bfloat16* __restrict__ Blo,
    float* __restrict__ C)
{
    extern __shared__ char smc[];
    const uint32_t sb = smem_to_u32(smc);
    const int tid = threadIdx.x, wid = tid >> 5, lane = tid & 31;
    const int bm = blockIdx.y * 128, bn = blockIdx.x * 128;

    // Loader role: threads 0-127 -> A(hi,lo), 128-255 -> B(hi,lo)
    const bool isA = tid < 128;
    const int t = isA ? tid : tid - 128;
    const __nv_bfloat16* srcHi = isA ? (Ahi + (size_t)bm * DMODEL)
                                     : (Bhi + (size_t)bn * DMODEL);
    const __nv_bfloat16* srcLo = isA ? (Alo + (size_t)bm * DMODEL)
                                     : (Blo + (size_t)bn * DMODEL);
    const uint32_t matHiOff = isA ? 0u : 2u * TILE_B;
    const uint32_t matLoOff = matHiOff + TILE_B;

    float acc[4][4][4];
#pragma unroll
    for (int i = 0; i < 4; i++)
#pragma unroll
        for (int j = 0; j < 4; j++)
#pragma unroll
            for (int e = 0; e < 4; e++) acc[i][j][e] = 0.f;

    const int mwarp = wid & 1, nwarp = wid >> 1;

    // ---- prologue: stage 0 ----
    {
        const int k0 = 0;
        const uint32_t base = sb;
#pragma unroll
        for (int i = 0; i < 4; i++) {
            int chunk = t + (i << 7);
            int row = chunk >> 2, seg = chunk & 3;
            uint32_t so = (uint32_t)(row * 40 + seg * 8) * 2;
            cp_async16(base + matHiOff + so, srcHi + (size_t)row * DMODEL + k0 + seg * 8);
            cp_async16(base + matLoOff + so, srcLo + (size_t)row * DMODEL + k0 + seg * 8);
        }
        asm volatile("cp.async.commit_group;" ::: "memory");
    }

    for (int c = 0; c < 32; c++) {
        if (c + 1 < 32) {
            const int k0 = (c + 1) << 5;
            const uint32_t base = sb + ((c + 1) & 1) * STAGE_B;
#pragma unroll
            for (int i = 0; i < 4; i++) {
                int chunk = t + (i << 7);
                int row = chunk >> 2, seg = chunk & 3;
                uint32_t so = (uint32_t)(row * 40 + seg * 8) * 2;
                cp_async16(base + matHiOff + so, srcHi + (size_t)row * DMODEL + k0 + seg * 8);
                cp_async16(base + matLoOff + so, srcLo + (size_t)row * DMODEL + k0 + seg * 8);
            }
            asm volatile("cp.async.commit_group;" ::: "memory");
            asm volatile("cp.async.wait_group 1;" ::: "memory");
        } else {
            asm volatile("cp.async.wait_group 0;" ::: "memory");
        }
        __syncthreads();

        // ---- compute stage c&1 ----
        const uint32_t aHi = sb + (c & 1) * STAGE_B;
        const uint32_t aLo = aHi + TILE_B;
        const uint32_t bHi = aHi + 2u * TILE_B;
        const uint32_t bLo = aHi + 3u * TILE_B;

#pragma unroll
        for (int ks = 0; ks < 2; ks++) {
            uint32_t af[4][4], alf[4][4], bfr[4][2], blf[4][2];
            const int arow = mwarp * 64 + (lane & 7) + ((lane >> 3) & 1) * 8;
            const int acol = ks * 16 + (lane >> 4) * 8;
#pragma unroll
            for (int mf = 0; mf < 4; mf++) {
                uint32_t off = (uint32_t)((arow + mf * 16) * 40 + acol) * 2;
                ldsm4(af[mf],  aHi + off);
                ldsm4(alf[mf], aLo + off);
            }
            const int l16 = lane & 15;
            const int brow = nwarp * 32 + (l16 & 7);
            const int bcol = ks * 16 + ((l16 >> 3) & 1) * 8;
#pragma unroll
            for (int nf = 0; nf < 4; nf++) {
                uint32_t off = (uint32_t)((brow + nf * 8) * 40 + bcol) * 2;
                ldsm2(bfr[nf], bHi + off);
                ldsm2(blf[nf], bLo + off);
            }
#pragma unroll
            for (int mf = 0; mf < 4; mf++)
#pragma unroll
                for (int nf = 0; nf < 4; nf++) {
                    mma_bf16(acc[mf][nf], af[mf],  bfr[nf]);
                    mma_bf16(acc[mf][nf], af[mf],  blf[nf]);
                    mma_bf16(acc[mf][nf], alf[mf], bfr[nf]);
                }
        }
        __syncthreads();
    }

    // ---- epilogue: direct fp32 stores (float2 per frag-row) ----
    const int rbase = bm + mwarp * 64 + (lane >> 2);
    const int cbase = bn + nwarp * 32 + (lane & 3) * 2;
#pragma unroll
    for (int mf = 0; mf < 4; mf++)
#pragma unroll
        for (int nf = 0; nf < 4; nf++) {
            size_t o0 = (size_t)(rbase + mf * 16) * DMODEL + cbase + nf * 8;
            *(float2*)&C[o0]                 = make_float2(acc[mf][nf][0], acc[mf][nf][1]);
            *(float2*)&C[o0 + 8 * DMODEL]    = make_float2(acc[mf][nf][2], acc[mf][nf][3]);
        }
}

// ---------------------------------------------------------------------------
// fp32 -> bf16 (hi, lo) split. Vectorized x4.
// ---------------------------------------------------------------------------
__global__ void split_bf16(const float* __restrict__ s,
                           __nv_bfloat16* __restrict__ hi,
                           __nv_bfloat16* __restrict__ lo, int n4)
{
    int i = blockIdx.x * blockDim.x + threadIdx.x;
    if (i >= n4) return;
    float4 v = ((const float4*)s)[i];
    __nv_bfloat16 h0 = __float2bfloat16(v.x), h1 = __float2bfloat16(v.y);
    __nv_bfloat16 h2 = __float2bfloat16(v.z), h3 = __float2bfloat16(v.w);
    __nv_bfloat16 l0 = __float2bfloat16(v.x - __bfloat162float(h0));
    __nv_bfloat16 l1 = __float2bfloat16(v.y - __bfloat162float(h1));
    __nv_bfloat16 l2 = __float2bfloat16(v.z - __bfloat162float(h2));
    __nv_bfloat16 l3 = __float2bfloat16(v.w - __bfloat162float(h3));
    ((__nv_bfloat162*)hi)[2 * i]     = __nv_bfloat162(h0, h1);
    ((__nv_bfloat162*)hi)[2 * i + 1] = __nv_bfloat162(h2, h3);
    ((__nv_bfloat162*)lo)[2 * i]     = __nv_bfloat162(l0, l1);
    ((__nv_bfloat162*)lo)[2 * i + 1] = __nv_bfloat162(l2, l3);
}

// ---------------------------------------------------------------------------
// RoPE: small fp64 cos/sin table (SEQ x 32), then memory-bound apply to Q & K.
// ---------------------------------------------------------------------------
__global__ void rope_table(float2* __restrict__ tab, const int* __restrict__ pos)
{
    int i = blockIdx.x * blockDim.x + threadIdx.x;
    if (i >= SEQ * 32) return;
    int fi = i & 31, s = i >> 5;
    double invf = exp2(-(double)fi * 0.41524101186091903);   // 10000^(-fi/32)
    float ang = (float)pos[s] * (float)invf;                 // fp32 round as ref
    double sd, cd;
    sincos((double)ang, &sd, &cd);
    tab[i] = make_float2((float)cd, (float)sd);
}

__global__ void rope_apply(float* __restrict__ q, float* __restrict__ k,
                           const float2* __restrict__ tab)
{
    const int NP = MTOT * 512;
    int p = blockIdx.x * blockDim.x + threadIdx.x;
    if (p >= NP) return;
    int sf = p >> 9, w = p & 511, fi = w & 31, h = w >> 5, s = sf & (SEQ - 1);
    float2 cs = tab[(s << 5) + fi];
    size_t off = (size_t)sf * DMODEL + h * DK + 2 * fi;

    float2* qp = (float2*)(q + off);
    float2 qv = *qp;
    *qp = make_float2(qv.x * cs.x - qv.y * cs.y, qv.y * cs.x + qv.x * cs.y);

    float2* kp = (float2*)(k + off);
    float2 kv = *kp;
    *kp = make_float2(kv.x * cs.x - kv.y * cs.y, kv.y * cs.x + kv.x * cs.y);
}

// ---------------------------------------------------------------------------
// Causal flash attention, fp32, online softmax (known-passing from R1).
// ---------------------------------------------------------------------------
__global__ __launch_bounds__(128) void attn_kernel(
    const float* __restrict__ Q, const float* __restrict__ K,
    const float* __restrict__ V, float* __restrict__ O)
{
    __shared__ float Ks[64][64];
    __shared__ float Vs[64][64];

    const int t    = threadIdx.x;
    const int row  = t >> 1;
    const int cb   = (t & 1) * 32;
    const int b    = blockIdx.z;
    const int h    = blockIdx.y;
    const int q0   = blockIdx.x * 64;
    const int qidx = q0 + row;

    const size_t base_bh = (size_t)b * SEQ * DMODEL + (size_t)h * DK;

    float qreg[32];
    {
        const float* qp = Q + base_bh + (size_t)qidx * DMODEL + cb;
#pragma unroll
        for (int j = 0; j < 32; j += 4)
            *(float4*)&qreg[j] = *(const float4*)(qp + j);
    }

    float m_i = -INFINITY, l_i = 0.f;
    float acc[32];
#pragma unroll
    for (int j = 0; j < 32; j++) acc[j] = 0.f;

    const int ktiles = (q0 >> 6) + 1;
    for (int kt = 0; kt < ktiles; kt++) {
        const float* kp = K + base_bh + (size_t)(kt * 64 + row) * DMODEL + cb;
        const float* vp = V + base_bh + (size_t)(kt * 64 + row) * DMODEL + cb;
#pragma unroll
        for (int j = 0; j < 32; j += 4) {
            *(float4*)&Ks[row][cb + j] = *(const float4*)(kp + j);
            *(float4*)&Vs[row][cb + j] = *(const float4*)(vp + j);
        }
        __syncthreads();

#pragma unroll 4
        for (int kc = 0; kc < 64; kc++) {
            int key = kt * 64 + kc;
            float partial = 0.f;
#pragma unroll
            for (int j = 0; j < 32; j++)
                partial = fmaf(qreg[j], Ks[kc][cb + j], partial);
            partial += __shfl_xor_sync(0xffffffffu, partial, 1);

            float s = (key <= qidx) ? partial * SCALE : -INFINITY;
            float m_new = fmaxf(m_i, s);
            float corr  = expf(m_i - m_new);
            float pexp  = expf(s - m_new);
            l_i = l_i * corr + pexp;
#pragma unroll
            for (int j = 0; j < 32; j++)
                acc[j] = fmaf(acc[j], corr, pexp * Vs[kc][cb + j]);
            m_i = m_new;
        }
        __syncthreads();
    }

    const float inv = 1.f / l_i;
    float* op = O + base_bh + (size_t)qidx * DMODEL + cb;
#pragma unroll
    for (int j = 0; j < 32; j += 4) {
        float4 o4 = make_float4(acc[j] * inv, acc[j + 1] * inv,
                                acc[j + 2] * inv, acc[j + 3] * inv);
        *(float4*)(op + j) = o4;
    }
}

// ---------------------------------------------------------------------------
// Launch
// ---------------------------------------------------------------------------
extern "C" void kernel_launch(void* const* d_in, const int* in_sizes, int n_in,
                              void* d_out, int out_size)
{
    const float* x  = (const float*)d_in[0];
    const float* Wq = (const float*)d_in[1];
    const float* Wk = (const float*)d_in[2];
    const float* Wv = (const float*)d_in[3];
    const float* Wo = (const float*)d_in[4];
    const int*   tp = (const int*)d_in[5];
    float* out = (float*)d_out;

    float *q, *k, *v, *o;
    __nv_bfloat16 *ahi, *alo, *whi, *wlo;
    float2* cs;
    cudaGetSymbolAddress((void**)&q,   g_q);
    cudaGetSymbolAddress((void**)&k,   g_k);
    cudaGetSymbolAddress((void**)&v,   g_v);
    cudaGetSymbolAddress((void**)&o,   g_o);
    cudaGetSymbolAddress((void**)&ahi, g_ahi);
    cudaGetSymbolAddress((void**)&alo, g_alo);
    cudaGetSymbolAddress((void**)&whi, g_whi);
    cudaGetSymbolAddress((void**)&wlo, g_wlo);
    cudaGetSymbolAddress((void**)&cs,  g_cs);

    cudaFuncSetAttribute(gemm_mma, cudaFuncAttributeMaxDynamicSharedMemorySize,
                         GEMM_SMEM);

    const int nx4 = MTOT * DMODEL / 4;
    const int nw4 = DMODEL * DMODEL / 4;
    dim3 ggrid(DMODEL / 128, MTOT / 128);   // (8, 32)

    // QKV projections (tensor cores, bf16x3)
    split_bf16<<<(nx4 + 255) / 256, 256>>>(x, ahi, alo, nx4);
    split_bf16<<<(nw4 + 255) / 256, 256>>>(Wq, whi, wlo, nw4);
    gemm_mma<<<ggrid, 256, GEMM_SMEM>>>(ahi, alo, whi, wlo, q);
    split_bf16<<<(nw4 + 255) / 256, 256>>>(Wk, whi, wlo, nw4);
    gemm_mma<<<ggrid, 256, GEMM_SMEM>>>(ahi, alo, whi, wlo, k);
    split_bf16<<<(nw4 + 255) / 256, 256>>>(Wv, whi, wlo, nw4);
    gemm_mma<<<ggrid, 256, GEMM_SMEM>>>(ahi, alo, whi, wlo, v);

    // RoPE
    rope_table<<<(SEQ * 32 + 255) / 256, 256>>>(cs, tp);
    const int NP = MTOT * 512;
    rope_apply<<<(NP + 255) / 256, 256>>>(q, k, cs);

    // Attention
    attn_kernel<<<dim3(SEQ / 64, NHEADS, BATCH), 128>>>(q, k, v, o);

    // Output projection
    split_bf16<<<(nx4 + 255) / 256, 256>>>(o, ahi, alo, nx4);
    split_bf16<<<(nw4 + 255) / 256, 256>>>(Wo, whi, wlo, nw4);
    gemm_mma<<<ggrid, 256, GEMM_SMEM>>>(ahi, alo, whi, wlo, out);
}

// round 5
// speedup vs baseline: 4.4539x; 3.1543x over previous
#include <cuda_runtime.h>
#include <cuda_bf16.h>
#include <math.h>
#include <stdint.h>

// ---------------------------------------------------------------------------
// Problem constants
// ---------------------------------------------------------------------------
#define BATCH   2
#define SEQ     2048
#define DMODEL  1024
#define NHEADS  16
#define DK      64
#define MTOT    (BATCH * SEQ)        // 4096
#define SCALE   0.125f               // 1/sqrt(64)

// ---------------------------------------------------------------------------
// Scratch (__device__ globals; allocation-free rule)
// ---------------------------------------------------------------------------
__device__ float g_q[MTOT * DMODEL];
__device__ float g_k[MTOT * DMODEL];
__device__ float g_v[MTOT * DMODEL];
__device__ float g_o[MTOT * DMODEL];
__device__ __nv_bfloat16 g_ahi[MTOT * DMODEL];
__device__ __nv_bfloat16 g_alo[MTOT * DMODEL];
__device__ __nv_bfloat16 g_whi[DMODEL * DMODEL];
__device__ __nv_bfloat16 g_wlo[DMODEL * DMODEL];
__device__ __nv_bfloat16 g_qhi[MTOT * DMODEL];
__device__ __nv_bfloat16 g_qlo[MTOT * DMODEL];
__device__ __nv_bfloat16 g_khi[MTOT * DMODEL];
__device__ __nv_bfloat16 g_klo[MTOT * DMODEL];
__device__ __nv_bfloat16 g_vthi[MTOT * DMODEL];
__device__ __nv_bfloat16 g_vtlo[MTOT * DMODEL];
__device__ float2 g_cs[SEQ * (DK / 2)];

// ---------------------------------------------------------------------------
// PTX helpers (portable sm_80+ tensor-core path)
// ---------------------------------------------------------------------------
__device__ __forceinline__ uint32_t smem_to_u32(const void* p) {
    uint32_t a;
    asm("{ .reg .u64 t; cvta.to.shared.u64 t, %1; cvt.u32.u64 %0, t; }"
        : "=r"(a) : "l"(p));
    return a;
}

__device__ __forceinline__ void cp_async16(uint32_t dst, const void* src) {
    asm volatile("cp.async.cg.shared.global [%0], [%1], 16;" :: "r"(dst), "l"(src));
}

__device__ __forceinline__ void ldsm4(uint32_t* r, uint32_t addr) {
    asm volatile("ldmatrix.sync.aligned.m8n8.x4.shared.b16 {%0,%1,%2,%3}, [%4];"
                 : "=r"(r[0]), "=r"(r[1]), "=r"(r[2]), "=r"(r[3]) : "r"(addr));
}

__device__ __forceinline__ void ldsm2(uint32_t* r, uint32_t addr) {
    asm volatile("ldmatrix.sync.aligned.m8n8.x2.shared.b16 {%0,%1}, [%2];"
                 : "=r"(r[0]), "=r"(r[1]) : "r"(addr));
}

__device__ __forceinline__ void mma_bf16(float* d, const uint32_t* a, const uint32_t* b) {
    asm volatile(
        "mma.sync.aligned.m16n8k16.row.col.f32.bf16.bf16.f32 "
        "{%0,%1,%2,%3}, {%4,%5,%6,%7}, {%8,%9}, {%0,%1,%2,%3};"
        : "+f"(d[0]), "+f"(d[1]), "+f"(d[2]), "+f"(d[3])
        : "r"(a[0]), "r"(a[1]), "r"(a[2]), "r"(a[3]), "r"(b[0]), "r"(b[1]));
}

__device__ __forceinline__ uint32_t pack2bf(float a, float b) {
    __nv_bfloat162 t = __floats2bfloat162_rn(a, b);
    return *reinterpret_cast<uint32_t*>(&t);
}
__device__ __forceinline__ float bf_round(float x) {
    return __bfloat162float(__float2bfloat16(x));
}

// ---------------------------------------------------------------------------
// GEMM (NT) via mma.sync bf16x3 (unchanged from R4 — passing at 1.5e-5)
// ---------------------------------------------------------------------------
#define TILE_B  10240u
#define STAGE_B 40960u
#define GEMM_SMEM (2 * STAGE_B)

__global__ __launch_bounds__(256) void gemm_mma(
    const __nv_bfloat16* __restrict__ Ahi, const __nv_bfloat16* __restrict__ Alo,
    const __nv_bfloat16* __restrict__ Bhi, const __nv_bfloat16* __restrict__ Blo,
    float* __restrict__ C)
{
    extern __shared__ char smc[];
    const uint32_t sb = smem_to_u32(smc);
    const int tid = threadIdx.x, wid = tid >> 5, lane = tid & 31;
    const int bm = blockIdx.y * 128, bn = blockIdx.x * 128;

    const bool isA = tid < 128;
    const int t = isA ? tid : tid - 128;
    const __nv_bfloat16* srcHi = isA ? (Ahi + (size_t)bm * DMODEL)
                                     : (Bhi + (size_t)bn * DMODEL);
    const __nv_bfloat16* srcLo = isA ? (Alo + (size_t)bm * DMODEL)
                                     : (Blo + (size_t)bn * DMODEL);
    const uint32_t matHiOff = isA ? 0u : 2u * TILE_B;
    const uint32_t matLoOff = matHiOff + TILE_B;

    float acc[4][4][4];
#pragma unroll
    for (int i = 0; i < 4; i++)
#pragma unroll
        for (int j = 0; j < 4; j++)
#pragma unroll
            for (int e = 0; e < 4; e++) acc[i][j][e] = 0.f;

    const int mwarp = wid & 1, nwarp = wid >> 1;

    {
        const uint32_t base = sb;
#pragma unroll
        for (int i = 0; i < 4; i++) {
            int chunk = t + (i << 7);
            int row = chunk >> 2, seg = chunk & 3;
            uint32_t so = (uint32_t)(row * 40 + seg * 8) * 2;
            cp_async16(base + matHiOff + so, srcHi + (size_t)row * DMODEL + seg * 8);
            cp_async16(base + matLoOff + so, srcLo + (size_t)row * DMODEL + seg * 8);
        }
        asm volatile("cp.async.commit_group;" ::: "memory");
    }

    for (int c = 0; c < 32; c++) {
        if (c + 1 < 32) {
            const int k0 = (c + 1) << 5;
            const uint32_t base = sb + ((c + 1) & 1) * STAGE_B;
#pragma unroll
            for (int i = 0; i < 4; i++) {
                int chunk = t + (i << 7);
                int row = chunk >> 2, seg = chunk & 3;
                uint32_t so = (uint32_t)(row * 40 + seg * 8) * 2;
                cp_async16(base + matHiOff + so, srcHi + (size_t)row * DMODEL + k0 + seg * 8);
                cp_async16(base + matLoOff + so, srcLo + (size_t)row * DMODEL + k0 + seg * 8);
            }
            asm volatile("cp.async.commit_group;" ::: "memory");
            asm volatile("cp.async.wait_group 1;" ::: "memory");
        } else {
            asm volatile("cp.async.wait_group 0;" ::: "memory");
        }
        __syncthreads();

        const uint32_t aHi = sb + (c & 1) * STAGE_B;
        const uint32_t aLo = aHi + TILE_B;
        const uint32_t bHi = aHi + 2u * TILE_B;
        const uint32_t bLo = aHi + 3u * TILE_B;

#pragma unroll
        for (int ks = 0; ks < 2; ks++) {
            uint32_t af[4][4], alf[4][4], bfr[4][2], blf[4][2];
            const int arow = mwarp * 64 + (lane & 7) + ((lane >> 3) & 1) * 8;
            const int acol = ks * 16 + (lane >> 4) * 8;
#pragma unroll
            for (int mf = 0; mf < 4; mf++) {
                uint32_t off = (uint32_t)((arow + mf * 16) * 40 + acol) * 2;
                ldsm4(af[mf],  aHi + off);
                ldsm4(alf[mf], aLo + off);
            }
            const int l16 = lane & 15;
            const int brow = nwarp * 32 + (l16 & 7);
            const int bcol = ks * 16 + ((l16 >> 3) & 1) * 8;
#pragma unroll
            for (int nf = 0; nf < 4; nf++) {
                uint32_t off = (uint32_t)((brow + nf * 8) * 40 + bcol) * 2;
                ldsm2(bfr[nf], bHi + off);
                ldsm2(blf[nf], bLo + off);
            }
#pragma unroll
            for (int mf = 0; mf < 4; mf++)
#pragma unroll
                for (int nf = 0; nf < 4; nf++) {
                    mma_bf16(acc[mf][nf], af[mf],  bfr[nf]);
                    mma_bf16(acc[mf][nf], af[mf],  blf[nf]);
                    mma_bf16(acc[mf][nf], alf[mf], bfr[nf]);
                }
        }
        __syncthreads();
    }

    const int rbase = bm + mwarp * 64 + (lane >> 2);
    const int cbase = bn + nwarp * 32 + (lane & 3) * 2;
#pragma unroll
    for (int mf = 0; mf < 4; mf++)
#pragma unroll
        for (int nf = 0; nf < 4; nf++) {
            size_t o0 = (size_t)(rbase + mf * 16) * DMODEL + cbase + nf * 8;
            *(float2*)&C[o0]              = make_float2(acc[mf][nf][0], acc[mf][nf][1]);
            *(float2*)&C[o0 + 8 * DMODEL] = make_float2(acc[mf][nf][2], acc[mf][nf][3]);
        }
}

// ---------------------------------------------------------------------------
// fp32 -> bf16 (hi, lo) split. Vectorized x4.
// ---------------------------------------------------------------------------
__global__ void split_bf16(const float* __restrict__ s,
                           __nv_bfloat16* __restrict__ hi,
                           __nv_bfloat16* __restrict__ lo, int n4)
{
    int i = blockIdx.x * blockDim.x + threadIdx.x;
    if (i >= n4) return;
    float4 v = ((const float4*)s)[i];
    __nv_bfloat16 h0 = __float2bfloat16(v.x), h1 = __float2bfloat16(v.y);
    __nv_bfloat16 h2 = __float2bfloat16(v.z), h3 = __float2bfloat16(v.w);
    __nv_bfloat16 l0 = __float2bfloat16(v.x - __bfloat162float(h0));
    __nv_bfloat16 l1 = __float2bfloat16(v.y - __bfloat162float(h1));
    __nv_bfloat16 l2 = __float2bfloat16(v.z - __bfloat162float(h2));
    __nv_bfloat16 l3 = __float2bfloat16(v.w - __bfloat162float(h3));
    ((__nv_bfloat162*)hi)[2 * i]     = __nv_bfloat162(h0, h1);
    ((__nv_bfloat162*)hi)[2 * i + 1] = __nv_bfloat162(h2, h3);
    ((__nv_bfloat162*)lo)[2 * i]     = __nv_bfloat162(l0, l1);
    ((__nv_bfloat162*)lo)[2 * i + 1] = __nv_bfloat162(l2, l3);
}

// ---------------------------------------------------------------------------
// RoPE table (fp64 trig once) + fused rotate/scale/split for Q and K.
// Q gets the 1/sqrt(dk) scale folded in (exact power of two).
// ---------------------------------------------------------------------------
__global__ void rope_table(float2* __restrict__ tab, const int* __restrict__ pos)
{
    int i = blockIdx.x * blockDim.x + threadIdx.x;
    if (i >= SEQ * 32) return;
    int fi = i & 31, s = i >> 5;
    double invf = exp2(-(double)fi * 0.41524101186091903);
    float ang = (float)pos[s] * (float)invf;
    double sd, cd;
    sincos((double)ang, &sd, &cd);
    tab[i] = make_float2((float)cd, (float)sd);
}

__global__ void rope_split(const float* __restrict__ q, const float* __restrict__ k,
                           const float2* __restrict__ tab,
                           __nv_bfloat16* __restrict__ qhi, __nv_bfloat16* __restrict__ qlo,
                           __nv_bfloat16* __restrict__ khi, __nv_bfloat16* __restrict__ klo)
{
    const int NP = MTOT * 512;
    int p = blockIdx.x * blockDim.x + threadIdx.x;
    if (p >= NP) return;
    int sf = p >> 9, w = p & 511, fi = w & 31, hh = w >> 5, s = sf & (SEQ - 1);
    float2 cs = tab[(s << 5) + fi];
    size_t off = (size_t)sf * DMODEL + hh * DK + 2 * fi;

    float2 qv = *(const float2*)(q + off);
    float qx = (qv.x * cs.x - qv.y * cs.y) * SCALE;
    float qy = (qv.y * cs.x + qv.x * cs.y) * SCALE;
    __nv_bfloat16 qhx = __float2bfloat16(qx), qhy = __float2bfloat16(qy);
    *(__nv_bfloat162*)(qhi + off) = __nv_bfloat162(qhx, qhy);
    *(__nv_bfloat162*)(qlo + off) = __nv_bfloat162(
        __float2bfloat16(qx - __bfloat162float(qhx)),
        __float2bfloat16(qy - __bfloat162float(qhy)));

    float2 kv = *(const float2*)(k + off);
    float kx = kv.x * cs.x - kv.y * cs.y;
    float ky = kv.y * cs.x + kv.x * cs.y;
    __nv_bfloat16 khx = __float2bfloat16(kx), khy = __float2bfloat16(ky);
    *(__nv_bfloat162*)(khi + off) = __nv_bfloat162(khx, khy);
    *(__nv_bfloat162*)(klo + off) = __nv_bfloat162(
        __float2bfloat16(kx - __bfloat162float(khx)),
        __float2bfloat16(ky - __bfloat162float(khy)));
}

// ---------------------------------------------------------------------------
// V transpose + split: v[b,s,h,d] fp32 -> vthi/vtlo[(b,h),d,s] bf16.
// ---------------------------------------------------------------------------
__global__ void vt_split(const float* __restrict__ v,
                         __nv_bfloat16* __restrict__ vthi,
                         __nv_bfloat16* __restrict__ vtlo)
{
    __shared__ float t[32][33];
    const int bh = blockIdx.z, bb = bh >> 4, hh = bh & 15;
    const int s0 = blockIdx.x * 32, d0 = blockIdx.y * 32;
    const int tx = threadIdx.x, ty = threadIdx.y;   // 32 x 8

#pragma unroll
    for (int r = 0; r < 32; r += 8)
        t[ty + r][tx] = v[((size_t)bb * SEQ + s0 + ty + r) * DMODEL + hh * DK + d0 + tx];
    __syncthreads();
#pragma unroll
    for (int r = 0; r < 32; r += 8) {
        int d = d0 + ty + r;
        float val = t[tx][ty + r];
        size_t o = ((size_t)(bb * NHEADS + hh) * DK + d) * SEQ + s0 + tx;
        __nv_bfloat16 hv = __float2bfloat16(val);
        vthi[o] = hv;
        vtlo[o] = __float2bfloat16(val - __bfloat162float(hv));
    }
}

// ---------------------------------------------------------------------------
// Tensor-core causal flash attention.
// CTA: one (b,h), 64 query rows, 4 warps x 16 rows. 64-key tiles.
// QK^T and PV via bf16x3 mma.sync; online softmax on register fragments.
// ---------------------------------------------------------------------------
#define AT_STRIDE_B 144u            // 72 bf16 padded row
#define AT_MAT      9216u           // 64 * 144
#define AT_SMEM     (10u * AT_MAT)  // Q(hi,lo) + 2 stages x (Khi,Klo,VThi,VTlo)

__device__ __forceinline__ void attn_issue_tile(
    uint32_t sb, int stage, int s0, int tid, size_t qk_base, size_t vt_base,
    const __nv_bfloat16* Khi, const __nv_bfloat16* Klo,
    const __nv_bfloat16* VThi, const __nv_bfloat16* VTlo)
{
    uint32_t base = sb + 2u * AT_MAT + (uint32_t)stage * 4u * AT_MAT;
#pragma unroll
    for (int i = 0; i < 4; i++) {
        int c = tid + i * 128, row = c >> 3, seg = c & 7;
        uint32_t so = (uint32_t)row * AT_STRIDE_B + seg * 16;
        cp_async16(base + so,              Khi  + qk_base + (size_t)(s0 + row) * DMODEL + seg * 8);
        cp_async16(base + AT_MAT + so,     Klo  + qk_base + (size_t)(s0 + row) * DMODEL + seg * 8);
        cp_async16(base + 2 * AT_MAT + so, VThi + vt_base + (size_t)row * SEQ + s0 + seg * 8);
        cp_async16(base + 3 * AT_MAT + so, VTlo + vt_base + (size_t)row * SEQ + s0 + seg * 8);
    }
    asm volatile("cp.async.commit_group;" ::: "memory");
}

__global__ __launch_bounds__(128) void attn_mma(
    const __nv_bfloat16* __restrict__ Qhi, const __nv_bfloat16* __restrict__ Qlo,
    const __nv_bfloat16* __restrict__ Khi, const __nv_bfloat16* __restrict__ Klo,
    const __nv_bfloat16* __restrict__ VThi, const __nv_bfloat16* __restrict__ VTlo,
    float* __restrict__ O)
{
    extern __shared__ char smc[];
    const uint32_t sb = smem_to_u32(smc);
    const int tid = threadIdx.x, wid = tid >> 5, lane = tid & 31;
    const int b = blockIdx.z, h = blockIdx.y, q0 = blockIdx.x * 64;

    const size_t qk_base = (size_t)b * SEQ * DMODEL + (size_t)h * DK;
    const size_t vt_base = ((size_t)(b * NHEADS + h)) * DK * SEQ;

    // --- one-time Q tile load (hi/lo) ---
#pragma unroll
    for (int i = 0; i < 4; i++) {
        int c = tid + i * 128, row = c >> 3, seg = c & 7;
        uint32_t so = (uint32_t)row * AT_STRIDE_B + seg * 16;
        cp_async16(sb + so,          Qhi + qk_base + (size_t)(q0 + row) * DMODEL + seg * 8);
        cp_async16(sb + AT_MAT + so, Qlo + qk_base + (size_t)(q0 + row) * DMODEL + seg * 8);
    }
    asm volatile("cp.async.commit_group;" ::: "memory");
    asm volatile("cp.async.wait_group 0;" ::: "memory");
    __syncthreads();

    uint32_t qh[4][4], ql[4][4];
    {
        const int arow = wid * 16 + (lane & 7) + ((lane >> 3) & 1) * 8;
#pragma unroll
        for (int ks = 0; ks < 4; ks++) {
            uint32_t off = (uint32_t)arow * AT_STRIDE_B + (uint32_t)(ks * 16 + (lane >> 4) * 8) * 2;
            ldsm4(qh[ks], sb + off);
            ldsm4(ql[ks], sb + AT_MAT + off);
        }
    }

    float o_acc[8][4];
#pragma unroll
    for (int nf = 0; nf < 8; nf++)
#pragma unroll
        for (int e = 0; e < 4; e++) o_acc[nf][e] = 0.f;
    float m0 = -INFINITY, m1 = -INFINITY, l0 = 0.f, l1 = 0.f;

    const int ktiles = (q0 >> 6) + 1;
    attn_issue_tile(sb, 0, 0, tid, qk_base, vt_base, Khi, Klo, VThi, VTlo);

    const int l16 = lane & 15;
    const int brow = l16 & 7;
    const int bcsel = ((l16 >> 3) & 1) * 8;

    for (int kt = 0; kt < ktiles; kt++) {
        asm volatile("cp.async.wait_group 0;" ::: "memory");
        __syncthreads();
        if (kt + 1 < ktiles)
            attn_issue_tile(sb, (kt + 1) & 1, (kt + 1) * 64, tid, qk_base, vt_base,
                            Khi, Klo, VThi, VTlo);

        const uint32_t kb_hi = sb + 2u * AT_MAT + (uint32_t)(kt & 1) * 4u * AT_MAT;
        const uint32_t kb_lo = kb_hi + AT_MAT;
        const uint32_t vb_hi = kb_hi + 2u * AT_MAT;
        const uint32_t vb_lo = kb_hi + 3u * AT_MAT;

        // ---- S = Q K^T (bf16x3) ----
        float sf[8][4];
#pragma unroll
        for (int nf = 0; nf < 8; nf++) {
            sf[nf][0] = sf[nf][1] = sf[nf][2] = sf[nf][3] = 0.f;
#pragma unroll
            for (int ks = 0; ks < 4; ks++) {
                uint32_t off = (uint32_t)(nf * 8 + brow) * AT_STRIDE_B
                             + (uint32_t)(ks * 16 + bcsel) * 2;
                uint32_t bh2[2], bl2[2];
                ldsm2(bh2, kb_hi + off);
                ldsm2(bl2, kb_lo + off);
                mma_bf16(sf[nf], qh[ks], bh2);
                mma_bf16(sf[nf], ql[ks], bh2);
                mma_bf16(sf[nf], qh[ks], bl2);
            }
        }

        const int r0 = q0 + wid * 16 + (lane >> 2);
        // ---- causal mask on diagonal tile ----
        if (kt == ktiles - 1) {
            const int kc0 = q0 + (lane & 3) * 2;
#pragma unroll
            for (int nf = 0; nf < 8; nf++) {
                int key = kc0 + nf * 8;
                if (key     > r0)     sf[nf][0] = -1e30f;
                if (key + 1 > r0)     sf[nf][1] = -1e30f;
                if (key     > r0 + 8) sf[nf][2] = -1e30f;
                if (key + 1 > r0 + 8) sf[nf][3] = -1e30f;
            }
        }

        // ---- online softmax ----
        float mt0 = sf[0][0], mt1 = sf[0][2];
#pragma unroll
        for (int nf = 0; nf < 8; nf++) {
            mt0 = fmaxf(mt0, fmaxf(sf[nf][0], sf[nf][1]));
            mt1 = fmaxf(mt1, fmaxf(sf[nf][2], sf[nf][3]));
        }
        mt0 = fmaxf(mt0, __shfl_xor_sync(0xffffffffu, mt0, 1));
        mt0 = fmaxf(mt0, __shfl_xor_sync(0xffffffffu, mt0, 2));
        mt1 = fmaxf(mt1, __shfl_xor_sync(0xffffffffu, mt1, 1));
        mt1 = fmaxf(mt1, __shfl_xor_sync(0xffffffffu, mt1, 2));

        float mn0 = fmaxf(m0, mt0), mn1 = fmaxf(m1, mt1);
        float c0 = __expf(m0 - mn0), c1 = __expf(m1 - mn1);

        float lt0 = 0.f, lt1 = 0.f;
#pragma unroll
        for (int nf = 0; nf < 8; nf++) {
            sf[nf][0] = __expf(sf[nf][0] - mn0);
            sf[nf][1] = __expf(sf[nf][1] - mn0);
            sf[nf][2] = __expf(sf[nf][2] - mn1);
            sf[nf][3] = __expf(sf[nf][3] - mn1);
            lt0 += sf[nf][0] + sf[nf][1];
            lt1 += sf[nf][2] + sf[nf][3];
        }
        lt0 += __shfl_xor_sync(0xffffffffu, lt0, 1);
        lt0 += __shfl_xor_sync(0xffffffffu, lt0, 2);
        lt1 += __shfl_xor_sync(0xffffffffu, lt1, 1);
        lt1 += __shfl_xor_sync(0xffffffffu, lt1, 2);

        l0 = l0 * c0 + lt0;  l1 = l1 * c1 + lt1;
        m0 = mn0;            m1 = mn1;

#pragma unroll
        for (int nf = 0; nf < 8; nf++) {
            o_acc[nf][0] *= c0; o_acc[nf][1] *= c0;
            o_acc[nf][2] *= c1; o_acc[nf][3] *= c1;
        }

        // ---- O += P V (bf16x3); P frags built from S frags in registers ----
#pragma unroll
        for (int ks = 0; ks < 4; ks++) {
            float p00 = sf[2 * ks][0],     p01 = sf[2 * ks][1];
            float p02 = sf[2 * ks][2],     p03 = sf[2 * ks][3];
            float p10 = sf[2 * ks + 1][0], p11 = sf[2 * ks + 1][1];
            float p12 = sf[2 * ks + 1][2], p13 = sf[2 * ks + 1][3];
            uint32_t ph[4], pl[4];
            ph[0] = pack2bf(p00, p01);
            ph[1] = pack2bf(p02, p03);
            ph[2] = pack2bf(p10, p11);
            ph[3] = pack2bf(p12, p13);
            pl[0] = pack2bf(p00 - bf_round(p00), p01 - bf_round(p01));
            pl[1] = pack2bf(p02 - bf_round(p02), p03 - bf_round(p03));
            pl[2] = pack2bf(p10 - bf_round(p10), p11 - bf_round(p11));
            pl[3] = pack2bf(p12 - bf_round(p12), p13 - bf_round(p13));
#pragma unroll
            for (int nf = 0; nf < 8; nf++) {
                uint32_t off = (uint32_t)(nf * 8 + brow) * AT_STRIDE_B
                             + (uint32_t)(ks * 16 + bcsel) * 2;
                uint32_t bh2[2], bl2[2];
                ldsm2(bh2, vb_hi + off);
                ldsm2(bl2, vb_lo + off);
                mma_bf16(o_acc[nf], ph, bh2);
                mma_bf16(o_acc[nf], pl, bh2);
                mma_bf16(o_acc[nf], ph, bl2);
            }
        }
    }

    // ---- epilogue ----
    const float inv0 = 1.f / l0, inv1 = 1.f / l1;
    const int row0 = q0 + wid * 16 + (lane >> 2);
#pragma unroll
    for (int nf = 0; nf < 8; nf++) {
        int col = nf * 8 + (lane & 3) * 2;
        *(float2*)&O[qk_base + (size_t)row0 * DMODEL + col] =
            make_float2(o_acc[nf][0] * inv0, o_acc[nf][1] * inv0);
        *(float2*)&O[qk_base + (size_t)(row0 + 8) * DMODEL + col] =
            make_float2(o_acc[nf][2] * inv1, o_acc[nf][3] * inv1);
    }
}

// ---------------------------------------------------------------------------
// Launch
// ---------------------------------------------------------------------------
extern "C" void kernel_launch(void* const* d_in, const int* in_sizes, int n_in,
                              void* d_out, int out_size)
{
    const float* x  = (const float*)d_in[0];
    const float* Wq = (const float*)d_in[1];
    const float* Wk = (const float*)d_in[2];
    const float* Wv = (const float*)d_in[3];
    const float* Wo = (const float*)d_in[4];
    const int*   tp = (const int*)d_in[5];
    float* out = (float*)d_out;

    float *q, *k, *v, *o;
    __nv_bfloat16 *ahi, *alo, *whi, *wlo, *qhi, *qlo, *khi, *klo, *vthi, *vtlo;
    float2* cs;
    cudaGetSymbolAddress((void**)&q,    g_q);
    cudaGetSymbolAddress((void**)&k,    g_k);
    cudaGetSymbolAddress((void**)&v,    g_v);
    cudaGetSymbolAddress((void**)&o,    g_o);
    cudaGetSymbolAddress((void**)&ahi,  g_ahi);
    cudaGetSymbolAddress((void**)&alo,  g_alo);
    cudaGetSymbolAddress((void**)&whi,  g_whi);
    cudaGetSymbolAddress((void**)&wlo,  g_wlo);
    cudaGetSymbolAddress((void**)&qhi,  g_qhi);
    cudaGetSymbolAddress((void**)&qlo,  g_qlo);
    cudaGetSymbolAddress((void**)&khi,  g_khi);
    cudaGetSymbolAddress((void**)&klo,  g_klo);
    cudaGetSymbolAddress((void**)&vthi, g_vthi);
    cudaGetSymbolAddress((void**)&vtlo, g_vtlo);
    cudaGetSymbolAddress((void**)&cs,   g_cs);

    cudaFuncSetAttribute(gemm_mma, cudaFuncAttributeMaxDynamicSharedMemorySize, GEMM_SMEM);
    cudaFuncSetAttribute(attn_mma, cudaFuncAttributeMaxDynamicSharedMemorySize, AT_SMEM);

    const int nx4 = MTOT * DMODEL / 4;
    const int nw4 = DMODEL * DMODEL / 4;
    dim3 ggrid(DMODEL / 128, MTOT / 128);

    // QKV projections
    split_bf16<<<(nx4 + 255) / 256, 256>>>(x, ahi, alo, nx4);
    split_bf16<<<(nw4 + 255) / 256, 256>>>(Wq, whi, wlo, nw4);
    gemm_mma<<<ggrid, 256, GEMM_SMEM>>>(ahi, alo, whi, wlo, q);
    split_bf16<<<(nw4 + 255) / 256, 256>>>(Wk, whi, wlo, nw4);
    gemm_mma<<<ggrid, 256, GEMM_SMEM>>>(ahi, alo, whi, wlo, k);
    split_bf16<<<(nw4 + 255) / 256, 256>>>(Wv, whi, wlo, nw4);
    gemm_mma<<<ggrid, 256, GEMM_SMEM>>>(ahi, alo, whi, wlo, v);

    // RoPE + operand prep for attention
    rope_table<<<(SEQ * 32 + 255) / 256, 256>>>(cs, tp);
    const int NP = MTOT * 512;
    rope_split<<<(NP + 255) / 256, 256>>>(q, k, cs, qhi, qlo, khi, klo);
    vt_split<<<dim3(SEQ / 32, DK / 32, BATCH * NHEADS), dim3(32, 8)>>>(v, vthi, vtlo);

    // Attention (tensor cores)
    attn_mma<<<dim3(SEQ / 64, NHEADS, BATCH), 128, AT_SMEM>>>(
        qhi, qlo, khi, klo, vthi, vtlo, o);

    // Output projection
    split_bf16<<<(nx4 + 255) / 256, 256>>>(o, ahi, alo, nx4);
    split_bf16<<<(nw4 + 255) / 256, 256>>>(Wo, whi, wlo, nw4);
    gemm_mma<<<ggrid, 256, GEMM_SMEM>>>(ahi, alo, whi, wlo, out);
}

// round 6
// speedup vs baseline: 4.5548x; 1.0226x over previous
#include <cuda_runtime.h>
#include <cuda_bf16.h>
#include <math.h>
#include <stdint.h>

// ---------------------------------------------------------------------------
// Problem constants
// ---------------------------------------------------------------------------
#define BATCH   2
#define SEQ     2048
#define DMODEL  1024
#define NHEADS  16
#define DK      64
#define MTOT    (BATCH * SEQ)        // 4096
#define SCALE   0.125f               // 1/sqrt(64)
#define WSZ     (DMODEL * DMODEL)

// ---------------------------------------------------------------------------
// Scratch (__device__ globals; allocation-free rule)
// ---------------------------------------------------------------------------
__device__ float g_v[MTOT * DMODEL];
__device__ __nv_bfloat16 g_ahi[MTOT * DMODEL];
__device__ __nv_bfloat16 g_alo[MTOT * DMODEL];
__device__ __nv_bfloat16 g_whi[4 * WSZ];
__device__ __nv_bfloat16 g_wlo[4 * WSZ];
__device__ __nv_bfloat16 g_qhi[MTOT * DMODEL];
__device__ __nv_bfloat16 g_qlo[MTOT * DMODEL];
__device__ __nv_bfloat16 g_khi[MTOT * DMODEL];
__device__ __nv_bfloat16 g_klo[MTOT * DMODEL];
__device__ __nv_bfloat16 g_vthi[MTOT * DMODEL];
__device__ __nv_bfloat16 g_vtlo[MTOT * DMODEL];
__device__ float2 g_cs[SEQ * (DK / 2)];

// ---------------------------------------------------------------------------
// PTX helpers
// ---------------------------------------------------------------------------
__device__ __forceinline__ uint32_t smem_to_u32(const void* p) {
    uint32_t a;
    asm("{ .reg .u64 t; cvta.to.shared.u64 t, %1; cvt.u32.u64 %0, t; }"
        : "=r"(a) : "l"(p));
    return a;
}

__device__ __forceinline__ void cp_async16(uint32_t dst, const void* src) {
    asm volatile("cp.async.cg.shared.global [%0], [%1], 16;" :: "r"(dst), "l"(src));
}

__device__ __forceinline__ void ldsm4(uint32_t* r, uint32_t addr) {
    asm volatile("ldmatrix.sync.aligned.m8n8.x4.shared.b16 {%0,%1,%2,%3}, [%4];"
                 : "=r"(r[0]), "=r"(r[1]), "=r"(r[2]), "=r"(r[3]) : "r"(addr));
}

__device__ __forceinline__ void ldsm2(uint32_t* r, uint32_t addr) {
    asm volatile("ldmatrix.sync.aligned.m8n8.x2.shared.b16 {%0,%1}, [%2];"
                 : "=r"(r[0]), "=r"(r[1]) : "r"(addr));
}

__device__ __forceinline__ void mma_bf16(float* d, const uint32_t* a, const uint32_t* b) {
    asm volatile(
        "mma.sync.aligned.m16n8k16.row.col.f32.bf16.bf16.f32 "
        "{%0,%1,%2,%3}, {%4,%5,%6,%7}, {%8,%9}, {%0,%1,%2,%3};"
        : "+f"(d[0]), "+f"(d[1]), "+f"(d[2]), "+f"(d[3])
        : "r"(a[0]), "r"(a[1]), "r"(a[2]), "r"(a[3]), "r"(b[0]), "r"(b[1]));
}

__device__ __forceinline__ uint32_t pack2bf(float a, float b) {
    __nv_bfloat162 t = __floats2bfloat162_rn(a, b);
    return *reinterpret_cast<uint32_t*>(&t);
}
__device__ __forceinline__ float bf_round(float x) {
    return __bfloat162float(__float2bfloat16(x));
}
// hi/lo split store of an adjacent pair
__device__ __forceinline__ void store_split2(
    __nv_bfloat16* hi, __nv_bfloat16* lo, size_t off, float a, float b)
{
    __nv_bfloat16 ha = __float2bfloat16(a), hb = __float2bfloat16(b);
    *(__nv_bfloat162*)(hi + off) = __nv_bfloat162(ha, hb);
    *(__nv_bfloat162*)(lo + off) = __nv_bfloat162(
        __float2bfloat16(a - __bfloat162float(ha)),
        __float2bfloat16(b - __bfloat162float(hb)));
}

// ---------------------------------------------------------------------------
// Shared GEMM mainloop (NT, bf16x3, 128x128 tile, BK=32, 2-stage cp.async)
// Computes acc[4][4][4] for this thread; caller provides epilogue.
// ---------------------------------------------------------------------------
#define TILE_B  10240u
#define STAGE_B 40960u
#define GEMM_SMEM (2 * STAGE_B)

__device__ __forceinline__ void gemm_mainloop(
    uint32_t sb, int tid, int wid, int lane,
    const __nv_bfloat16* __restrict__ Ahi, const __nv_bfloat16* __restrict__ Alo,
    const __nv_bfloat16* __restrict__ Bhi, const __nv_bfloat16* __restrict__ Blo,
    int bm, int bn, float acc[4][4][4])
{
    const bool isA = tid < 128;
    const int t = isA ? tid : tid - 128;
    const __nv_bfloat16* srcHi = isA ? (Ahi + (size_t)bm * DMODEL)
                                     : (Bhi + (size_t)bn * DMODEL);
    const __nv_bfloat16* srcLo = isA ? (Alo + (size_t)bm * DMODEL)
                                     : (Blo + (size_t)bn * DMODEL);
    const uint32_t matHiOff = isA ? 0u : 2u * TILE_B;
    const uint32_t matLoOff = matHiOff + TILE_B;

#pragma unroll
    for (int i = 0; i < 4; i++)
#pragma unroll
        for (int j = 0; j < 4; j++)
#pragma unroll
            for (int e = 0; e < 4; e++) acc[i][j][e] = 0.f;

    const int mwarp = wid & 1, nwarp = wid >> 1;

    {
#pragma unroll
        for (int i = 0; i < 4; i++) {
            int chunk = t + (i << 7);
            int row = chunk >> 2, seg = chunk & 3;
            uint32_t so = (uint32_t)(row * 40 + seg * 8) * 2;
            cp_async16(sb + matHiOff + so, srcHi + (size_t)row * DMODEL + seg * 8);
            cp_async16(sb + matLoOff + so, srcLo + (size_t)row * DMODEL + seg * 8);
        }
        asm volatile("cp.async.commit_group;" ::: "memory");
    }

    for (int c = 0; c < 32; c++) {
        if (c + 1 < 32) {
            const int k0 = (c + 1) << 5;
            const uint32_t base = sb + ((c + 1) & 1) * STAGE_B;
#pragma unroll
            for (int i = 0; i < 4; i++) {
                int chunk = t + (i << 7);
                int row = chunk >> 2, seg = chunk & 3;
                uint32_t so = (uint32_t)(row * 40 + seg * 8) * 2;
                cp_async16(base + matHiOff + so, srcHi + (size_t)row * DMODEL + k0 + seg * 8);
                cp_async16(base + matLoOff + so, srcLo + (size_t)row * DMODEL + k0 + seg * 8);
            }
            asm volatile("cp.async.commit_group;" ::: "memory");
            asm volatile("cp.async.wait_group 1;" ::: "memory");
        } else {
            asm volatile("cp.async.wait_group 0;" ::: "memory");
        }
        __syncthreads();

        const uint32_t aHi = sb + (c & 1) * STAGE_B;
        const uint32_t aLo = aHi + TILE_B;
        const uint32_t bHi = aHi + 2u * TILE_B;
        const uint32_t bLo = aHi + 3u * TILE_B;

#pragma unroll
        for (int ks = 0; ks < 2; ks++) {
            uint32_t af[4][4], alf[4][4], bfr[4][2], blf[4][2];
            const int arow = mwarp * 64 + (lane & 7) + ((lane >> 3) & 1) * 8;
            const int acol = ks * 16 + (lane >> 4) * 8;
#pragma unroll
            for (int mf = 0; mf < 4; mf++) {
                uint32_t off = (uint32_t)((arow + mf * 16) * 40 + acol) * 2;
                ldsm4(af[mf],  aHi + off);
                ldsm4(alf[mf], aLo + off);
            }
            const int l16 = lane & 15;
            const int brow = nwarp * 32 + (l16 & 7);
            const int bcol = ks * 16 + ((l16 >> 3) & 1) * 8;
#pragma unroll
            for (int nf = 0; nf < 4; nf++) {
                uint32_t off = (uint32_t)((brow + nf * 8) * 40 + bcol) * 2;
                ldsm2(bfr[nf], bHi + off);
                ldsm2(blf[nf], bLo + off);
            }
#pragma unroll
            for (int mf = 0; mf < 4; mf++)
#pragma unroll
                for (int nf = 0; nf < 4; nf++) {
                    mma_bf16(acc[mf][nf], af[mf],  bfr[nf]);
                    mma_bf16(acc[mf][nf], af[mf],  blf[nf]);
                    mma_bf16(acc[mf][nf], alf[mf], bfr[nf]);
                }
        }
        __syncthreads();
    }
}

// ---------------------------------------------------------------------------
// QKV GEMM: grid.z selects output. z=0: Q (rope+scale, bf16 hi/lo split);
// z=1: K (rope, split); z=2: V (plain fp32 for the later transpose).
// ---------------------------------------------------------------------------
__global__ __launch_bounds__(256) void gemm_qkv(
    const __nv_bfloat16* __restrict__ Ahi, const __nv_bfloat16* __restrict__ Alo,
    const __nv_bfloat16* __restrict__ Whi, const __nv_bfloat16* __restrict__ Wlo,
    __nv_bfloat16* __restrict__ qhi, __nv_bfloat16* __restrict__ qlo,
    __nv_bfloat16* __restrict__ khi, __nv_bfloat16* __restrict__ klo,
    float* __restrict__ V, const float2* __restrict__ tab)
{
    extern __shared__ char smc[];
    const uint32_t sb = smem_to_u32(smc);
    const int tid = threadIdx.x, wid = tid >> 5, lane = tid & 31;
    const int bm = blockIdx.y * 128, bn = blockIdx.x * 128;
    const int z = blockIdx.z;

    float acc[4][4][4];
    gemm_mainloop(sb, tid, wid, lane, Ahi, Alo,
                  Whi + (size_t)z * WSZ, Wlo + (size_t)z * WSZ, bm, bn, acc);

    const int mwarp = wid & 1, nwarp = wid >> 1;
    const int rbase = bm + mwarp * 64 + (lane >> 2);
    const int cbase = bn + nwarp * 32 + (lane & 3) * 2;

    if (z == 2) {
#pragma unroll
        for (int mf = 0; mf < 4; mf++)
#pragma unroll
            for (int nf = 0; nf < 4; nf++) {
                size_t o0 = (size_t)(rbase + mf * 16) * DMODEL + cbase + nf * 8;
                *(float2*)&V[o0]              = make_float2(acc[mf][nf][0], acc[mf][nf][1]);
                *(float2*)&V[o0 + 8 * DMODEL] = make_float2(acc[mf][nf][2], acc[mf][nf][3]);
            }
        return;
    }

    const float sc = (z == 0) ? SCALE : 1.0f;
    __nv_bfloat16* hi = (z == 0) ? qhi : khi;
    __nv_bfloat16* lo = (z == 0) ? qlo : klo;
#pragma unroll
    for (int mf = 0; mf < 4; mf++)
#pragma unroll
        for (int nf = 0; nf < 4; nf++) {
            const int col = cbase + nf * 8;
            const int fi  = (col & 63) >> 1;
#pragma unroll
            for (int g = 0; g < 2; g++) {
                const int tok = rbase + mf * 16 + g * 8;
                const float2 cs = tab[((tok & (SEQ - 1)) << 5) + fi];
                float e = acc[mf][nf][2 * g], o = acc[mf][nf][2 * g + 1];
                float oe = (e * cs.x - o * cs.y) * sc;
                float oo = (o * cs.x + e * cs.y) * sc;
                store_split2(hi, lo, (size_t)tok * DMODEL + col, oe, oo);
            }
        }
}

// ---------------------------------------------------------------------------
// Output-projection GEMM: plain fp32 C (final result).
// ---------------------------------------------------------------------------
__global__ __launch_bounds__(256) void gemm_out(
    const __nv_bfloat16* __restrict__ Ahi, const __nv_bfloat16* __restrict__ Alo,
    const __nv_bfloat16* __restrict__ Bhi, const __nv_bfloat16* __restrict__ Blo,
    float* __restrict__ C)
{
    extern __shared__ char smc[];
    const uint32_t sb = smem_to_u32(smc);
    const int tid = threadIdx.x, wid = tid >> 5, lane = tid & 31;
    const int bm = blockIdx.y * 128, bn = blockIdx.x * 128;

    float acc[4][4][4];
    gemm_mainloop(sb, tid, wid, lane, Ahi, Alo, Bhi, Blo, bm, bn, acc);

    const int mwarp = wid & 1, nwarp = wid >> 1;
    const int rbase = bm + mwarp * 64 + (lane >> 2);
    const int cbase = bn + nwarp * 32 + (lane & 3) * 2;
#pragma unroll
    for (int mf = 0; mf < 4; mf++)
#pragma unroll
        for (int nf = 0; nf < 4; nf++) {
            size_t o0 = (size_t)(rbase + mf * 16) * DMODEL + cbase + nf * 8;
            *(float2*)&C[o0]              = make_float2(acc[mf][nf][0], acc[mf][nf][1]);
            *(float2*)&C[o0 + 8 * DMODEL] = make_float2(acc[mf][nf][2], acc[mf][nf][3]);
        }
}

// ---------------------------------------------------------------------------
// Splits: x -> hi/lo; 4 weights -> hi/lo slots (one launch).
// ---------------------------------------------------------------------------
__global__ void split_bf16(const float* __restrict__ s,
                           __nv_bfloat16* __restrict__ hi,
                           __nv_bfloat16* __restrict__ lo, int n4)
{
    int i = blockIdx.x * blockDim.x + threadIdx.x;
    if (i >= n4) return;
    float4 v = ((const float4*)s)[i];
    __nv_bfloat16 h0 = __float2bfloat16(v.x), h1 = __float2bfloat16(v.y);
    __nv_bfloat16 h2 = __float2bfloat16(v.z), h3 = __float2bfloat16(v.w);
    ((__nv_bfloat162*)hi)[2 * i]     = __nv_bfloat162(h0, h1);
    ((__nv_bfloat162*)hi)[2 * i + 1] = __nv_bfloat162(h2, h3);
    ((__nv_bfloat162*)lo)[2 * i]     = __nv_bfloat162(
        __float2bfloat16(v.x - __bfloat162float(h0)),
        __float2bfloat16(v.y - __bfloat162float(h1)));
    ((__nv_bfloat162*)lo)[2 * i + 1] = __nv_bfloat162(
        __float2bfloat16(v.z - __bfloat162float(h2)),
        __float2bfloat16(v.w - __bfloat162float(h3)));
}

__global__ void split_w4(const float* __restrict__ w0, const float* __restrict__ w1,
                         const float* __restrict__ w2, const float* __restrict__ w3,
                         __nv_bfloat16* __restrict__ hi, __nv_bfloat16* __restrict__ lo)
{
    const int nw4 = WSZ / 4;
    int i = blockIdx.x * blockDim.x + threadIdx.x;
    if (i >= 4 * nw4) return;
    int z = i / nw4, r = i - z * nw4;
    const float* src = (z == 0) ? w0 : (z == 1) ? w1 : (z == 2) ? w2 : w3;
    float4 v = ((const float4*)src)[r];
    __nv_bfloat16* hz = hi + (size_t)z * WSZ;
    __nv_bfloat16* lz = lo + (size_t)z * WSZ;
    __nv_bfloat16 h0 = __float2bfloat16(v.x), h1 = __float2bfloat16(v.y);
    __nv_bfloat16 h2 = __float2bfloat16(v.z), h3 = __float2bfloat16(v.w);
    ((__nv_bfloat162*)hz)[2 * r]     = __nv_bfloat162(h0, h1);
    ((__nv_bfloat162*)hz)[2 * r + 1] = __nv_bfloat162(h2, h3);
    ((__nv_bfloat162*)lz)[2 * r]     = __nv_bfloat162(
        __float2bfloat16(v.x - __bfloat162float(h0)),
        __float2bfloat16(v.y - __bfloat162float(h1)));
    ((__nv_bfloat162*)lz)[2 * r + 1] = __nv_bfloat162(
        __float2bfloat16(v.z - __bfloat162float(h2)),
        __float2bfloat16(v.w - __bfloat162float(h3)));
}

// ---------------------------------------------------------------------------
// RoPE table (fp64 trig once).
// ---------------------------------------------------------------------------
__global__ void rope_table(float2* __restrict__ tab, const int* __restrict__ pos)
{
    int i = blockIdx.x * blockDim.x + threadIdx.x;
    if (i >= SEQ * 32) return;
    int fi = i & 31, s = i >> 5;
    double invf = exp2(-(double)fi * 0.41524101186091903);
    float ang = (float)pos[s] * (float)invf;
    double sd, cd;
    sincos((double)ang, &sd, &cd);
    tab[i] = make_float2((float)cd, (float)sd);
}

// ---------------------------------------------------------------------------
// V transpose + split: v[b,s,h,d] fp32 -> vthi/vtlo[(b,h),d,s] bf16.
// ---------------------------------------------------------------------------
__global__ void vt_split(const float* __restrict__ v,
                         __nv_bfloat16* __restrict__ vthi,
                         __nv_bfloat16* __restrict__ vtlo)
{
    __shared__ float t[32][33];
    const int bh = blockIdx.z, bb = bh >> 4, hh = bh & 15;
    const int s0 = blockIdx.x * 32, d0 = blockIdx.y * 32;
    const int tx = threadIdx.x, ty = threadIdx.y;

#pragma unroll
    for (int r = 0; r < 32; r += 8)
        t[ty + r][tx] = v[((size_t)bb * SEQ + s0 + ty + r) * DMODEL + hh * DK + d0 + tx];
    __syncthreads();
#pragma unroll
    for (int r = 0; r < 32; r += 8) {
        int d = d0 + ty + r;
        float val = t[tx][ty + r];
        size_t o = ((size_t)(bb * NHEADS + hh) * DK + d) * SEQ + s0 + tx;
        __nv_bfloat16 hv = __float2bfloat16(val);
        vthi[o] = hv;
        vtlo[o] = __float2bfloat16(val - __bfloat162float(hv));
    }
}

// ---------------------------------------------------------------------------
// Tensor-core causal flash attention. 128 query rows / CTA, 256 threads,
// 8 warps x 16 rows, 64-key double-buffered tiles. Output: bf16 hi/lo split.
// ---------------------------------------------------------------------------
#define AQ_MAT      18432u           // 128 * 144
#define AK_MAT      9216u            // 64 * 144
#define AT_STRIDE_B 144u
#define AT_SMEM     (2u * AQ_MAT + 8u * AK_MAT)   // 110592 B

__device__ __forceinline__ void attn_issue_tile(
    uint32_t sb, int stage, int s0, int tid, size_t qk_base, size_t vt_base,
    const __nv_bfloat16* Khi, const __nv_bfloat16* Klo,
    const __nv_bfloat16* VThi, const __nv_bfloat16* VTlo)
{
    uint32_t base = sb + 2u * AQ_MAT + (uint32_t)stage * 4u * AK_MAT;
#pragma unroll
    for (int i = 0; i < 2; i++) {
        int c = tid + i * 256, row = c >> 3, seg = c & 7;
        uint32_t so = (uint32_t)row * AT_STRIDE_B + seg * 16;
        cp_async16(base + so,              Khi  + qk_base + (size_t)(s0 + row) * DMODEL + seg * 8);
        cp_async16(base + AK_MAT + so,     Klo  + qk_base + (size_t)(s0 + row) * DMODEL + seg * 8);
        cp_async16(base + 2 * AK_MAT + so, VThi + vt_base + (size_t)row * SEQ + s0 + seg * 8);
        cp_async16(base + 3 * AK_MAT + so, VTlo + vt_base + (size_t)row * SEQ + s0 + seg * 8);
    }
    asm volatile("cp.async.commit_group;" ::: "memory");
}

__global__ __launch_bounds__(256, 1) void attn_mma(
    const __nv_bfloat16* __restrict__ Qhi, const __nv_bfloat16* __restrict__ Qlo,
    const __nv_bfloat16* __restrict__ Khi, const __nv_bfloat16* __restrict__ Klo,
    const __nv_bfloat16* __restrict__ VThi, const __nv_bfloat16* __restrict__ VTlo,
    __nv_bfloat16* __restrict__ Ohi, __nv_bfloat16* __restrict__ Olo)
{
    extern __shared__ char smc[];
    const uint32_t sb = smem_to_u32(smc);
    const int tid = threadIdx.x, wid = tid >> 5, lane = tid & 31;
    const int b = blockIdx.z, h = blockIdx.y;
    const int q0 = (gridDim.x - 1 - blockIdx.x) * 128;   // heavy CTAs first

    const size_t qk_base = (size_t)b * SEQ * DMODEL + (size_t)h * DK;
    const size_t vt_base = ((size_t)(b * NHEADS + h)) * DK * SEQ;

    // --- one-time Q tile load (hi/lo), 128 rows ---
#pragma unroll
    for (int i = 0; i < 4; i++) {
        int c = tid + i * 256, row = c >> 3, seg = c & 7;
        uint32_t so = (uint32_t)row * AT_STRIDE_B + seg * 16;
        cp_async16(sb + so,          Qhi + qk_base + (size_t)(q0 + row) * DMODEL + seg * 8);
        cp_async16(sb + AQ_MAT + so, Qlo + qk_base + (size_t)(q0 + row) * DMODEL + seg * 8);
    }
    asm volatile("cp.async.commit_group;" ::: "memory");
    asm volatile("cp.async.wait_group 0;" ::: "memory");
    __syncthreads();

    uint32_t qh[4][4], ql[4][4];
    {
        const int arow = wid * 16 + (lane & 7) + ((lane >> 3) & 1) * 8;
#pragma unroll
        for (int ks = 0; ks < 4; ks++) {
            uint32_t off = (uint32_t)arow * AT_STRIDE_B + (uint32_t)(ks * 16 + (lane >> 4) * 8) * 2;
            ldsm4(qh[ks], sb + off);
            ldsm4(ql[ks], sb + AQ_MAT + off);
        }
    }

    float o_acc[8][4];
#pragma unroll
    for (int nf = 0; nf < 8; nf++)
#pragma unroll
        for (int e = 0; e < 4; e++) o_acc[nf][e] = 0.f;
    float m0 = -INFINITY, m1 = -INFINITY, l0 = 0.f, l1 = 0.f;

    const int ktiles = (q0 >> 6) + 2;
    attn_issue_tile(sb, 0, 0, tid, qk_base, vt_base, Khi, Klo, VThi, VTlo);

    const int l16 = lane & 15;
    const int brow = l16 & 7;
    const int bcsel = ((l16 >> 3) & 1) * 8;
    const int r0 = q0 + wid * 16 + (lane >> 2);

    for (int kt = 0; kt < ktiles; kt++) {
        asm volatile("cp.async.wait_group 0;" ::: "memory");
        __syncthreads();
        if (kt + 1 < ktiles)
            attn_issue_tile(sb, (kt + 1) & 1, (kt + 1) * 64, tid, qk_base, vt_base,
                            Khi, Klo, VThi, VTlo);

        const uint32_t kb_hi = sb + 2u * AQ_MAT + (uint32_t)(kt & 1) * 4u * AK_MAT;
        const uint32_t kb_lo = kb_hi + AK_MAT;
        const uint32_t vb_hi = kb_hi + 2u * AK_MAT;
        const uint32_t vb_lo = kb_hi + 3u * AK_MAT;

        // ---- S = Q K^T (bf16x3) ----
        float sf[8][4];
#pragma unroll
        for (int nf = 0; nf < 8; nf++) {
            sf[nf][0] = sf[nf][1] = sf[nf][2] = sf[nf][3] = 0.f;
#pragma unroll
            for (int ks = 0; ks < 4; ks++) {
                uint32_t off = (uint32_t)(nf * 8 + brow) * AT_STRIDE_B
                             + (uint32_t)(ks * 16 + bcsel) * 2;
                uint32_t bh2[2], bl2[2];
                ldsm2(bh2, kb_hi + off);
                ldsm2(bl2, kb_lo + off);
                mma_bf16(sf[nf], qh[ks], bh2);
                mma_bf16(sf[nf], ql[ks], bh2);
                mma_bf16(sf[nf], qh[ks], bl2);
            }
        }

        // ---- causal mask (near-diagonal tiles) ----
        if (kt >= ktiles - 2) {
            const int kc0 = kt * 64 + (lane & 3) * 2;
#pragma unroll
            for (int nf = 0; nf < 8; nf++) {
                int key = kc0 + nf * 8;
                if (key     > r0)     sf[nf][0] = -1e30f;
                if (key + 1 > r0)     sf[nf][1] = -1e30f;
                if (key     > r0 + 8) sf[nf][2] = -1e30f;
                if (key + 1 > r0 + 8) sf[nf][3] = -1e30f;
            }
        }

        // ---- online softmax ----
        float mt0 = sf[0][0], mt1 = sf[0][2];
#pragma unroll
        for (int nf = 0; nf < 8; nf++) {
            mt0 = fmaxf(mt0, fmaxf(sf[nf][0], sf[nf][1]));
            mt1 = fmaxf(mt1, fmaxf(sf[nf][2], sf[nf][3]));
        }
        mt0 = fmaxf(mt0, __shfl_xor_sync(0xffffffffu, mt0, 1));
        mt0 = fmaxf(mt0, __shfl_xor_sync(0xffffffffu, mt0, 2));
        mt1 = fmaxf(mt1, __shfl_xor_sync(0xffffffffu, mt1, 1));
        mt1 = fmaxf(mt1, __shfl_xor_sync(0xffffffffu, mt1, 2));

        float mn0 = fmaxf(m0, mt0), mn1 = fmaxf(m1, mt1);
        float c0 = __expf(m0 - mn0), c1 = __expf(m1 - mn1);

        float lt0 = 0.f, lt1 = 0.f;
#pragma unroll
        for (int nf = 0; nf < 8; nf++) {
            sf[nf][0] = __expf(sf[nf][0] - mn0);
            sf[nf][1] = __expf(sf[nf][1] - mn0);
            sf[nf][2] = __expf(sf[nf][2] - mn1);
            sf[nf][3] = __expf(sf[nf][3] - mn1);
            lt0 += sf[nf][0] + sf[nf][1];
            lt1 += sf[nf][2] + sf[nf][3];
        }
        lt0 += __shfl_xor_sync(0xffffffffu, lt0, 1);
        lt0 += __shfl_xor_sync(0xffffffffu, lt0, 2);
        lt1 += __shfl_xor_sync(0xffffffffu, lt1, 1);
        lt1 += __shfl_xor_sync(0xffffffffu, lt1, 2);

        l0 = l0 * c0 + lt0;  l1 = l1 * c1 + lt1;
        m0 = mn0;            m1 = mn1;

#pragma unroll
        for (int nf = 0; nf < 8; nf++) {
            o_acc[nf][0] *= c0; o_acc[nf][1] *= c0;
            o_acc[nf][2] *= c1; o_acc[nf][3] *= c1;
        }

        // ---- O += P V (bf16x3) ----
#pragma unroll
        for (int ks = 0; ks < 4; ks++) {
            float p00 = sf[2 * ks][0],     p01 = sf[2 * ks][1];
            float p02 = sf[2 * ks][2],     p03 = sf[2 * ks][3];
            float p10 = sf[2 * ks + 1][0], p11 = sf[2 * ks + 1][1];
            float p12 = sf[2 * ks + 1][2], p13 = sf[2 * ks + 1][3];
            uint32_t ph[4], pl[4];
            ph[0] = pack2bf(p00, p01);
            ph[1] = pack2bf(p02, p03);
            ph[2] = pack2bf(p10, p11);
            ph[3] = pack2bf(p12, p13);
            pl[0] = pack2bf(p00 - bf_round(p00), p01 - bf_round(p01));
            pl[1] = pack2bf(p02 - bf_round(p02), p03 - bf_round(p03));
            pl[2] = pack2bf(p10 - bf_round(p10), p11 - bf_round(p11));
            pl[3] = pack2bf(p12 - bf_round(p12), p13 - bf_round(p13));
#pragma unroll
            for (int nf = 0; nf < 8; nf++) {
                uint32_t off = (uint32_t)(nf * 8 + brow) * AT_STRIDE_B
                             + (uint32_t)(ks * 16 + bcsel) * 2;
                uint32_t bh2[2], bl2[2];
                ldsm2(bh2, vb_hi + off);
                ldsm2(bl2, vb_lo + off);
                mma_bf16(o_acc[nf], ph, bh2);
                mma_bf16(o_acc[nf], pl, bh2);
                mma_bf16(o_acc[nf], ph, bl2);
            }
        }
    }

    // ---- epilogue: normalize + hi/lo split store ----
    const float inv0 = 1.f / l0, inv1 = 1.f / l1;
#pragma unroll
    for (int nf = 0; nf < 8; nf++) {
        int col = nf * 8 + (lane & 3) * 2;
        store_split2(Ohi, Olo, qk_base + (size_t)r0 * DMODEL + col,
                     o_acc[nf][0] * inv0, o_acc[nf][1] * inv0);
        store_split2(Ohi, Olo, qk_base + (size_t)(r0 + 8) * DMODEL + col,
                     o_acc[nf][2] * inv1, o_acc[nf][3] * inv1);
    }
}

// ---------------------------------------------------------------------------
// Launch
// ---------------------------------------------------------------------------
extern "C" void kernel_launch(void* const* d_in, const int* in_sizes, int n_in,
                              void* d_out, int out_size)
{
    const float* x  = (const float*)d_in[0];
    const float* Wq = (const float*)d_in[1];
    const float* Wk = (const float*)d_in[2];
    const float* Wv = (const float*)d_in[3];
    const float* Wo = (const float*)d_in[4];
    const int*   tp = (const int*)d_in[5];
    float* out = (float*)d_out;

    float* v;
    __nv_bfloat16 *ahi, *alo, *whi, *wlo, *qhi, *qlo, *khi, *klo, *vthi, *vtlo;
    float2* cs;
    cudaGetSymbolAddress((void**)&v,    g_v);
    cudaGetSymbolAddress((void**)&ahi,  g_ahi);
    cudaGetSymbolAddress((void**)&alo,  g_alo);
    cudaGetSymbolAddress((void**)&whi,  g_whi);
    cudaGetSymbolAddress((void**)&wlo,  g_wlo);
    cudaGetSymbolAddress((void**)&qhi,  g_qhi);
    cudaGetSymbolAddress((void**)&qlo,  g_qlo);
    cudaGetSymbolAddress((void**)&khi,  g_khi);
    cudaGetSymbolAddress((void**)&klo,  g_klo);
    cudaGetSymbolAddress((void**)&vthi, g_vthi);
    cudaGetSymbolAddress((void**)&vtlo, g_vtlo);
    cudaGetSymbolAddress((void**)&cs,   g_cs);

    cudaFuncSetAttribute(gemm_qkv, cudaFuncAttributeMaxDynamicSharedMemorySize, GEMM_SMEM);
    cudaFuncSetAttribute(gemm_out, cudaFuncAttributeMaxDynamicSharedMemorySize, GEMM_SMEM);
    cudaFuncSetAttribute(attn_mma, cudaFuncAttributeMaxDynamicSharedMemorySize, AT_SMEM);

    const int nx4 = MTOT * DMODEL / 4;
    const int nwAll = WSZ;            // 4 * (WSZ/4) threads for split_w4

    // operand prep
    split_bf16<<<(nx4 + 255) / 256, 256>>>(x, ahi, alo, nx4);
    split_w4<<<(nwAll + 255) / 256, 256>>>(Wq, Wk, Wv, Wo, whi, wlo);
    rope_table<<<(SEQ * 32 + 255) / 256, 256>>>(cs, tp);

    // fused QKV projection (+rope/scale/split for Q,K)
    gemm_qkv<<<dim3(DMODEL / 128, MTOT / 128, 3), 256, GEMM_SMEM>>>(
        ahi, alo, whi, wlo, qhi, qlo, khi, klo, v, cs);

    // V transpose + split
    vt_split<<<dim3(SEQ / 32, DK / 32, BATCH * NHEADS), dim3(32, 8)>>>(v, vthi, vtlo);

    // attention (tensor cores), writes hi/lo split directly into a-buffers
    attn_mma<<<dim3(SEQ / 128, NHEADS, BATCH), 256, AT_SMEM>>>(
        qhi, qlo, khi, klo, vthi, vtlo, ahi, alo);

    // output projection
    gemm_out<<<dim3(DMODEL / 128, MTOT / 128), 256, GEMM_SMEM>>>(
        ahi, alo, whi + (size_t)3 * WSZ, wlo + (size_t)3 * WSZ, out);
}

// round 7
// speedup vs baseline: 5.0896x; 1.1174x over previous
#include <cuda_runtime.h>
#include <cuda_bf16.h>
#include <math.h>
#include <stdint.h>

// ---------------------------------------------------------------------------
// Problem constants
// ---------------------------------------------------------------------------
#define BATCH   2
#define SEQ     2048
#define DMODEL  1024
#define NHEADS  16
#define DK      64
#define MTOT    (BATCH * SEQ)        // 4096
#define SCALE   0.125f               // 1/sqrt(64)
#define WSZ     (DMODEL * DMODEL)

// ---------------------------------------------------------------------------
// Scratch (__device__ globals; allocation-free rule)
// ---------------------------------------------------------------------------
__device__ float g_v[MTOT * DMODEL];
__device__ __nv_bfloat16 g_ahi[MTOT * DMODEL];
__device__ __nv_bfloat16 g_alo[MTOT * DMODEL];
__device__ __nv_bfloat16 g_whi[4 * WSZ];
__device__ __nv_bfloat16 g_wlo[4 * WSZ];
__device__ __nv_bfloat16 g_qhi[MTOT * DMODEL];
__device__ __nv_bfloat16 g_qlo[MTOT * DMODEL];
__device__ __nv_bfloat16 g_khi[MTOT * DMODEL];
__device__ __nv_bfloat16 g_klo[MTOT * DMODEL];
__device__ __nv_bfloat16 g_vthi[MTOT * DMODEL];
__device__ __nv_bfloat16 g_vtlo[MTOT * DMODEL];
__device__ float2 g_cs[SEQ * (DK / 2)];

// ---------------------------------------------------------------------------
// PTX helpers
// ---------------------------------------------------------------------------
__device__ __forceinline__ uint32_t smem_to_u32(const void* p) {
    uint32_t a;
    asm("{ .reg .u64 t; cvta.to.shared.u64 t, %1; cvt.u32.u64 %0, t; }"
        : "=r"(a) : "l"(p));
    return a;
}

__device__ __forceinline__ void cp_async16(uint32_t dst, const void* src) {
    asm volatile("cp.async.cg.shared.global [%0], [%1], 16;" :: "r"(dst), "l"(src));
}

__device__ __forceinline__ void ldsm4(uint32_t* r, uint32_t addr) {
    asm volatile("ldmatrix.sync.aligned.m8n8.x4.shared.b16 {%0,%1,%2,%3}, [%4];"
                 : "=r"(r[0]), "=r"(r[1]), "=r"(r[2]), "=r"(r[3]) : "r"(addr));
}

__device__ __forceinline__ void ldsm2(uint32_t* r, uint32_t addr) {
    asm volatile("ldmatrix.sync.aligned.m8n8.x2.shared.b16 {%0,%1}, [%2];"
                 : "=r"(r[0]), "=r"(r[1]) : "r"(addr));
}

__device__ __forceinline__ void mma_bf16(float* d, const uint32_t* a, const uint32_t* b) {
    asm volatile(
        "mma.sync.aligned.m16n8k16.row.col.f32.bf16.bf16.f32 "
        "{%0,%1,%2,%3}, {%4,%5,%6,%7}, {%8,%9}, {%0,%1,%2,%3};"
        : "+f"(d[0]), "+f"(d[1]), "+f"(d[2]), "+f"(d[3])
        : "r"(a[0]), "r"(a[1]), "r"(a[2]), "r"(a[3]), "r"(b[0]), "r"(b[1]));
}

__device__ __forceinline__ uint32_t pack2bf(float a, float b) {
    __nv_bfloat162 t = __floats2bfloat162_rn(a, b);
    return *reinterpret_cast<uint32_t*>(&t);
}
__device__ __forceinline__ float bf_round(float x) {
    return __bfloat162float(__float2bfloat16(x));
}
__device__ __forceinline__ void store_split2(
    __nv_bfloat16* hi, __nv_bfloat16* lo, size_t off, float a, float b)
{
    __nv_bfloat16 ha = __float2bfloat16(a), hb = __float2bfloat16(b);
    *(__nv_bfloat162*)(hi + off) = __nv_bfloat162(ha, hb);
    *(__nv_bfloat162*)(lo + off) = __nv_bfloat162(
        __float2bfloat16(a - __bfloat162float(ha)),
        __float2bfloat16(b - __bfloat162float(hb)));
}

// ---------------------------------------------------------------------------
// Shared GEMM mainloop (NT, bf16x3, 128x128 tile, BK=32, 2-stage cp.async)
// Register-lean ordering: af*bhi, af*blo, then late-load alf*bhi.
// ---------------------------------------------------------------------------
#define TILE_B  10240u
#define STAGE_B 40960u
#define GEMM_SMEM (2 * STAGE_B)

__device__ __forceinline__ void gemm_mainloop(
    uint32_t sb, int tid, int wid, int lane,
    const __nv_bfloat16* __restrict__ Ahi, const __nv_bfloat16* __restrict__ Alo,
    const __nv_bfloat16* __restrict__ Bhi, const __nv_bfloat16* __restrict__ Blo,
    int bm, int bn, float acc[4][4][4])
{
    const bool isA = tid < 128;
    const int t = isA ? tid : tid - 128;
    const __nv_bfloat16* srcHi = isA ? (Ahi + (size_t)bm * DMODEL)
                                     : (Bhi + (size_t)bn * DMODEL);
    const __nv_bfloat16* srcLo = isA ? (Alo + (size_t)bm * DMODEL)
                                     : (Blo + (size_t)bn * DMODEL);
    const uint32_t matHiOff = isA ? 0u : 2u * TILE_B;
    const uint32_t matLoOff = matHiOff + TILE_B;

#pragma unroll
    for (int i = 0; i < 4; i++)
#pragma unroll
        for (int j = 0; j < 4; j++)
#pragma unroll
            for (int e = 0; e < 4; e++) acc[i][j][e] = 0.f;

    const int mwarp = wid & 1, nwarp = wid >> 1;

    {
#pragma unroll
        for (int i = 0; i < 4; i++) {
            int chunk = t + (i << 7);
            int row = chunk >> 2, seg = chunk & 3;
            uint32_t so = (uint32_t)(row * 40 + seg * 8) * 2;
            cp_async16(sb + matHiOff + so, srcHi + (size_t)row * DMODEL + seg * 8);
            cp_async16(sb + matLoOff + so, srcLo + (size_t)row * DMODEL + seg * 8);
        }
        asm volatile("cp.async.commit_group;" ::: "memory");
    }

    for (int c = 0; c < 32; c++) {
        if (c + 1 < 32) {
            const int k0 = (c + 1) << 5;
            const uint32_t base = sb + ((c + 1) & 1) * STAGE_B;
#pragma unroll
            for (int i = 0; i < 4; i++) {
                int chunk = t + (i << 7);
                int row = chunk >> 2, seg = chunk & 3;
                uint32_t so = (uint32_t)(row * 40 + seg * 8) * 2;
                cp_async16(base + matHiOff + so, srcHi + (size_t)row * DMODEL + k0 + seg * 8);
                cp_async16(base + matLoOff + so, srcLo + (size_t)row * DMODEL + k0 + seg * 8);
            }
            asm volatile("cp.async.commit_group;" ::: "memory");
            asm volatile("cp.async.wait_group 1;" ::: "memory");
        } else {
            asm volatile("cp.async.wait_group 0;" ::: "memory");
        }
        __syncthreads();

        const uint32_t aHi = sb + (c & 1) * STAGE_B;
        const uint32_t aLo = aHi + TILE_B;
        const uint32_t bHi = aHi + 2u * TILE_B;
        const uint32_t bLo = aHi + 3u * TILE_B;

#pragma unroll
        for (int ks = 0; ks < 2; ks++) {
            const int arow = mwarp * 64 + (lane & 7) + ((lane >> 3) & 1) * 8;
            const int acol = ks * 16 + (lane >> 4) * 8;
            const int l16 = lane & 15;
            const int brow = nwarp * 32 + (l16 & 7);
            const int bcol = ks * 16 + ((l16 >> 3) & 1) * 8;

            // Pass A-hi: load af + both B frags
            uint32_t af[4][4], bfr[4][2], blf[4][2];
#pragma unroll
            for (int mf = 0; mf < 4; mf++) {
                uint32_t off = (uint32_t)((arow + mf * 16) * 40 + acol) * 2;
                ldsm4(af[mf], aHi + off);
            }
#pragma unroll
            for (int nf = 0; nf < 4; nf++) {
                uint32_t off = (uint32_t)((brow + nf * 8) * 40 + bcol) * 2;
                ldsm2(bfr[nf], bHi + off);
                ldsm2(blf[nf], bLo + off);
            }
#pragma unroll
            for (int mf = 0; mf < 4; mf++)
#pragma unroll
                for (int nf = 0; nf < 4; nf++)
                    mma_bf16(acc[mf][nf], af[mf], bfr[nf]);
#pragma unroll
            for (int mf = 0; mf < 4; mf++)
#pragma unroll
                for (int nf = 0; nf < 4; nf++)
                    mma_bf16(acc[mf][nf], af[mf], blf[nf]);   // blf dead after

            // Pass A-lo: late load (af dead) -> lower peak register pressure
            uint32_t alf[4][4];
#pragma unroll
            for (int mf = 0; mf < 4; mf++) {
                uint32_t off = (uint32_t)((arow + mf * 16) * 40 + acol) * 2;
                ldsm4(alf[mf], aLo + off);
            }
#pragma unroll
            for (int mf = 0; mf < 4; mf++)
#pragma unroll
                for (int nf = 0; nf < 4; nf++)
                    mma_bf16(acc[mf][nf], alf[mf], bfr[nf]);
        }
        __syncthreads();
    }
}

// ---------------------------------------------------------------------------
// QKV GEMM (2 CTAs/SM): z=0 Q (rope+scale+split), z=1 K (rope+split), z=2 V.
// ---------------------------------------------------------------------------
__global__ __launch_bounds__(256, 2) void gemm_qkv(
    const __nv_bfloat16* __restrict__ Ahi, const __nv_bfloat16* __restrict__ Alo,
    const __nv_bfloat16* __restrict__ Whi, const __nv_bfloat16* __restrict__ Wlo,
    __nv_bfloat16* __restrict__ qhi, __nv_bfloat16* __restrict__ qlo,
    __nv_bfloat16* __restrict__ khi, __nv_bfloat16* __restrict__ klo,
    float* __restrict__ V, const float2* __restrict__ tab)
{
    extern __shared__ char smc[];
    const uint32_t sb = smem_to_u32(smc);
    const int tid = threadIdx.x, wid = tid >> 5, lane = tid & 31;
    const int bm = blockIdx.y * 128, bn = blockIdx.x * 128;
    const int z = blockIdx.z;

    float acc[4][4][4];
    gemm_mainloop(sb, tid, wid, lane, Ahi, Alo,
                  Whi + (size_t)z * WSZ, Wlo + (size_t)z * WSZ, bm, bn, acc);

    const int mwarp = wid & 1, nwarp = wid >> 1;
    const int rbase = bm + mwarp * 64 + (lane >> 2);
    const int cbase = bn + nwarp * 32 + (lane & 3) * 2;

    if (z == 2) {
#pragma unroll
        for (int mf = 0; mf < 4; mf++)
#pragma unroll
            for (int nf = 0; nf < 4; nf++) {
                size_t o0 = (size_t)(rbase + mf * 16) * DMODEL + cbase + nf * 8;
                *(float2*)&V[o0]              = make_float2(acc[mf][nf][0], acc[mf][nf][1]);
                *(float2*)&V[o0 + 8 * DMODEL] = make_float2(acc[mf][nf][2], acc[mf][nf][3]);
            }
        return;
    }

    const float sc = (z == 0) ? SCALE : 1.0f;
    __nv_bfloat16* hi = (z == 0) ? qhi : khi;
    __nv_bfloat16* lo = (z == 0) ? qlo : klo;
#pragma unroll
    for (int mf = 0; mf < 4; mf++)
#pragma unroll
        for (int nf = 0; nf < 4; nf++) {
            const int col = cbase + nf * 8;
            const int fi  = (col & 63) >> 1;
#pragma unroll
            for (int g = 0; g < 2; g++) {
                const int tok = rbase + mf * 16 + g * 8;
                const float2 cs = tab[((tok & (SEQ - 1)) << 5) + fi];
                float e = acc[mf][nf][2 * g], o = acc[mf][nf][2 * g + 1];
                float oe = (e * cs.x - o * cs.y) * sc;
                float oo = (o * cs.x + e * cs.y) * sc;
                store_split2(hi, lo, (size_t)tok * DMODEL + col, oe, oo);
            }
        }
}

// ---------------------------------------------------------------------------
// Output-projection GEMM (2 CTAs/SM): plain fp32 C.
// ---------------------------------------------------------------------------
__global__ __launch_bounds__(256, 2) void gemm_out(
    const __nv_bfloat16* __restrict__ Ahi, const __nv_bfloat16* __restrict__ Alo,
    const __nv_bfloat16* __restrict__ Bhi, const __nv_bfloat16* __restrict__ Blo,
    float* __restrict__ C)
{
    extern __shared__ char smc[];
    const uint32_t sb = smem_to_u32(smc);
    const int tid = threadIdx.x, wid = tid >> 5, lane = tid & 31;
    const int bm = blockIdx.y * 128, bn = blockIdx.x * 128;

    float acc[4][4][4];
    gemm_mainloop(sb, tid, wid, lane, Ahi, Alo, Bhi, Blo, bm, bn, acc);

    const int mwarp = wid & 1, nwarp = wid >> 1;
    const int rbase = bm + mwarp * 64 + (lane >> 2);
    const int cbase = bn + nwarp * 32 + (lane & 3) * 2;
#pragma unroll
    for (int mf = 0; mf < 4; mf++)
#pragma unroll
        for (int nf = 0; nf < 4; nf++) {
            size_t o0 = (size_t)(rbase + mf * 16) * DMODEL + cbase + nf * 8;
            *(float2*)&C[o0]              = make_float2(acc[mf][nf][0], acc[mf][nf][1]);
            *(float2*)&C[o0 + 8 * DMODEL] = make_float2(acc[mf][nf][2], acc[mf][nf][3]);
        }
}

// ---------------------------------------------------------------------------
// Splits
// ---------------------------------------------------------------------------
__global__ void split_bf16(const float* __restrict__ s,
                           __nv_bfloat16* __restrict__ hi,
                           __nv_bfloat16* __restrict__ lo, int n4)
{
    int i = blockIdx.x * blockDim.x + threadIdx.x;
    if (i >= n4) return;
    float4 v = ((const float4*)s)[i];
    __nv_bfloat16 h0 = __float2bfloat16(v.x), h1 = __float2bfloat16(v.y);
    __nv_bfloat16 h2 = __float2bfloat16(v.z), h3 = __float2bfloat16(v.w);
    ((__nv_bfloat162*)hi)[2 * i]     = __nv_bfloat162(h0, h1);
    ((__nv_bfloat162*)hi)[2 * i + 1] = __nv_bfloat162(h2, h3);
    ((__nv_bfloat162*)lo)[2 * i]     = __nv_bfloat162(
        __float2bfloat16(v.x - __bfloat162float(h0)),
        __float2bfloat16(v.y - __bfloat162float(h1)));
    ((__nv_bfloat162*)lo)[2 * i + 1] = __nv_bfloat162(
        __float2bfloat16(v.z - __bfloat162float(h2)),
        __float2bfloat16(v.w - __bfloat162float(h3)));
}

__global__ void split_w4(const float* __restrict__ w0, const float* __restrict__ w1,
                         const float* __restrict__ w2, const float* __restrict__ w3,
                         __nv_bfloat16* __restrict__ hi, __nv_bfloat16* __restrict__ lo)
{
    const int nw4 = WSZ / 4;
    int i = blockIdx.x * blockDim.x + threadIdx.x;
    if (i >= 4 * nw4) return;
    int z = i / nw4, r = i - z * nw4;
    const float* src = (z == 0) ? w0 : (z == 1) ? w1 : (z == 2) ? w2 : w3;
    float4 v = ((const float4*)src)[r];
    __nv_bfloat16* hz = hi + (size_t)z * WSZ;
    __nv_bfloat16* lz = lo + (size_t)z * WSZ;
    __nv_bfloat16 h0 = __float2bfloat16(v.x), h1 = __float2bfloat16(v.y);
    __nv_bfloat16 h2 = __float2bfloat16(v.z), h3 = __float2bfloat16(v.w);
    ((__nv_bfloat162*)hz)[2 * r]     = __nv_bfloat162(h0, h1);
    ((__nv_bfloat162*)hz)[2 * r + 1] = __nv_bfloat162(h2, h3);
    ((__nv_bfloat162*)lz)[2 * r]     = __nv_bfloat162(
        __float2bfloat16(v.x - __bfloat162float(h0)),
        __float2bfloat16(v.y - __bfloat162float(h1)));
    ((__nv_bfloat162*)lz)[2 * r + 1] = __nv_bfloat162(
        __float2bfloat16(v.z - __bfloat162float(h2)),
        __float2bfloat16(v.w - __bfloat162float(h3)));
}

// ---------------------------------------------------------------------------
// RoPE table
// ---------------------------------------------------------------------------
__global__ void rope_table(float2* __restrict__ tab, const int* __restrict__ pos)
{
    int i = blockIdx.x * blockDim.x + threadIdx.x;
    if (i >= SEQ * 32) return;
    int fi = i & 31, s = i >> 5;
    double invf = exp2(-(double)fi * 0.41524101186091903);
    float ang = (float)pos[s] * (float)invf;
    double sd, cd;
    sincos((double)ang, &sd, &cd);
    tab[i] = make_float2((float)cd, (float)sd);
}

// ---------------------------------------------------------------------------
// V transpose + split
// ---------------------------------------------------------------------------
__global__ void vt_split(const float* __restrict__ v,
                         __nv_bfloat16* __restrict__ vthi,
                         __nv_bfloat16* __restrict__ vtlo)
{
    __shared__ float t[32][33];
    const int bh = blockIdx.z, bb = bh >> 4, hh = bh & 15;
    const int s0 = blockIdx.x * 32, d0 = blockIdx.y * 32;
    const int tx = threadIdx.x, ty = threadIdx.y;

#pragma unroll
    for (int r = 0; r < 32; r += 8)
        t[ty + r][tx] = v[((size_t)bb * SEQ + s0 + ty + r) * DMODEL + hh * DK + d0 + tx];
    __syncthreads();
#pragma unroll
    for (int r = 0; r < 32; r += 8) {
        int d = d0 + ty + r;
        float val = t[tx][ty + r];
        size_t o = ((size_t)(bb * NHEADS + hh) * DK + d) * SEQ + s0 + tx;
        __nv_bfloat16 hv = __float2bfloat16(val);
        vthi[o] = hv;
        vtlo[o] = __float2bfloat16(val - __bfloat162float(hv));
    }
}

// ---------------------------------------------------------------------------
// Tensor-core causal flash attention (unchanged from R6).
// ---------------------------------------------------------------------------
#define AQ_MAT      18432u
#define AK_MAT      9216u
#define AT_STRIDE_B 144u
#define AT_SMEM     (2u * AQ_MAT + 8u * AK_MAT)

__device__ __forceinline__ void attn_issue_tile(
    uint32_t sb, int stage, int s0, int tid, size_t qk_base, size_t vt_base,
    const __nv_bfloat16* Khi, const __nv_bfloat16* Klo,
    const __nv_bfloat16* VThi, const __nv_bfloat16* VTlo)
{
    uint32_t base = sb + 2u * AQ_MAT + (uint32_t)stage * 4u * AK_MAT;
#pragma unroll
    for (int i = 0; i < 2; i++) {
        int c = tid + i * 256, row = c >> 3, seg = c & 7;
        uint32_t so = (uint32_t)row * AT_STRIDE_B + seg * 16;
        cp_async16(base + so,              Khi  + qk_base + (size_t)(s0 + row) * DMODEL + seg * 8);
        cp_async16(base + AK_MAT + so,     Klo  + qk_base + (size_t)(s0 + row) * DMODEL + seg * 8);
        cp_async16(base + 2 * AK_MAT + so, VThi + vt_base + (size_t)row * SEQ + s0 + seg * 8);
        cp_async16(base + 3 * AK_MAT + so, VTlo + vt_base + (size_t)row * SEQ + s0 + seg * 8);
    }
    asm volatile("cp.async.commit_group;" ::: "memory");
}

__global__ __launch_bounds__(256, 1) void attn_mma(
    const __nv_bfloat16* __restrict__ Qhi, const __nv_bfloat16* __restrict__ Qlo,
    const __nv_bfloat16* __restrict__ Khi, const __nv_bfloat16* __restrict__ Klo,
    const __nv_bfloat16* __restrict__ VThi, const __nv_bfloat16* __restrict__ VTlo,
    __nv_bfloat16* __restrict__ Ohi, __nv_bfloat16* __restrict__ Olo)
{
    extern __shared__ char smc[];
    const uint32_t sb = smem_to_u32(smc);
    const int tid = threadIdx.x, wid = tid >> 5, lane = tid & 31;
    const int b = blockIdx.z, h = blockIdx.y;
    const int q0 = (gridDim.x - 1 - blockIdx.x) * 128;

    const size_t qk_base = (size_t)b * SEQ * DMODEL + (size_t)h * DK;
    const size_t vt_base = ((size_t)(b * NHEADS + h)) * DK * SEQ;

#pragma unroll
    for (int i = 0; i < 4; i++) {
        int c = tid + i * 256, row = c >> 3, seg = c & 7;
        uint32_t so = (uint32_t)row * AT_STRIDE_B + seg * 16;
        cp_async16(sb + so,          Qhi + qk_base + (size_t)(q0 + row) * DMODEL + seg * 8);
        cp_async16(sb + AQ_MAT + so, Qlo + qk_base + (size_t)(q0 + row) * DMODEL + seg * 8);
    }
    asm volatile("cp.async.commit_group;" ::: "memory");
    asm volatile("cp.async.wait_group 0;" ::: "memory");
    __syncthreads();

    uint32_t qh[4][4], ql[4][4];
    {
        const int arow = wid * 16 + (lane & 7) + ((lane >> 3) & 1) * 8;
#pragma unroll
        for (int ks = 0; ks < 4; ks++) {
            uint32_t off = (uint32_t)arow * AT_STRIDE_B + (uint32_t)(ks * 16 + (lane >> 4) * 8) * 2;
            ldsm4(qh[ks], sb + off);
            ldsm4(ql[ks], sb + AQ_MAT + off);
        }
    }

    float o_acc[8][4];
#pragma unroll
    for (int nf = 0; nf < 8; nf++)
#pragma unroll
        for (int e = 0; e < 4; e++) o_acc[nf][e] = 0.f;
    float m0 = -INFINITY, m1 = -INFINITY, l0 = 0.f, l1 = 0.f;

    const int ktiles = (q0 >> 6) + 2;
    attn_issue_tile(sb, 0, 0, tid, qk_base, vt_base, Khi, Klo, VThi, VTlo);

    const int l16 = lane & 15;
    const int brow = l16 & 7;
    const int bcsel = ((l16 >> 3) & 1) * 8;
    const int r0 = q0 + wid * 16 + (lane >> 2);

    for (int kt = 0; kt < ktiles; kt++) {
        asm volatile("cp.async.wait_group 0;" ::: "memory");
        __syncthreads();
        if (kt + 1 < ktiles)
            attn_issue_tile(sb, (kt + 1) & 1, (kt + 1) * 64, tid, qk_base, vt_base,
                            Khi, Klo, VThi, VTlo);

        const uint32_t kb_hi = sb + 2u * AQ_MAT + (uint32_t)(kt & 1) * 4u * AK_MAT;
        const uint32_t kb_lo = kb_hi + AK_MAT;
        const uint32_t vb_hi = kb_hi + 2u * AK_MAT;
        const uint32_t vb_lo = kb_hi + 3u * AK_MAT;

        float sf[8][4];
#pragma unroll
        for (int nf = 0; nf < 8; nf++) {
            sf[nf][0] = sf[nf][1] = sf[nf][2] = sf[nf][3] = 0.f;
#pragma unroll
            for (int ks = 0; ks < 4; ks++) {
                uint32_t off = (uint32_t)(nf * 8 + brow) * AT_STRIDE_B
                             + (uint32_t)(ks * 16 + bcsel) * 2;
                uint32_t bh2[2], bl2[2];
                ldsm2(bh2, kb_hi + off);
                ldsm2(bl2, kb_lo + off);
                mma_bf16(sf[nf], qh[ks], bh2);
                mma_bf16(sf[nf], ql[ks], bh2);
                mma_bf16(sf[nf], qh[ks], bl2);
            }
        }

        if (kt >= ktiles - 2) {
            const int kc0 = kt * 64 + (lane & 3) * 2;
#pragma unroll
            for (int nf = 0; nf < 8; nf++) {
                int key = kc0 + nf * 8;
                if (key     > r0)     sf[nf][0] = -1e30f;
                if (key + 1 > r0)     sf[nf][1] = -1e30f;
                if (key     > r0 + 8) sf[nf][2] = -1e30f;
                if (key + 1 > r0 + 8) sf[nf][3] = -1e30f;
            }
        }

        float mt0 = sf[0][0], mt1 = sf[0][2];
#pragma unroll
        for (int nf = 0; nf < 8; nf++) {
            mt0 = fmaxf(mt0, fmaxf(sf[nf][0], sf[nf][1]));
            mt1 = fmaxf(mt1, fmaxf(sf[nf][2], sf[nf][3]));
        }
        mt0 = fmaxf(mt0, __shfl_xor_sync(0xffffffffu, mt0, 1));
        mt0 = fmaxf(mt0, __shfl_xor_sync(0xffffffffu, mt0, 2));
        mt1 = fmaxf(mt1, __shfl_xor_sync(0xffffffffu, mt1, 1));
        mt1 = fmaxf(mt1, __shfl_xor_sync(0xffffffffu, mt1, 2));

        float mn0 = fmaxf(m0, mt0), mn1 = fmaxf(m1, mt1);
        float c0 = __expf(m0 - mn0), c1 = __expf(m1 - mn1);

        float lt0 = 0.f, lt1 = 0.f;
#pragma unroll
        for (int nf = 0; nf < 8; nf++) {
            sf[nf][0] = __expf(sf[nf][0] - mn0);
            sf[nf][1] = __expf(sf[nf][1] - mn0);
            sf[nf][2] = __expf(sf[nf][2] - mn1);
            sf[nf][3] = __expf(sf[nf][3] - mn1);
            lt0 += sf[nf][0] + sf[nf][1];
            lt1 += sf[nf][2] + sf[nf][3];
        }
        lt0 += __shfl_xor_sync(0xffffffffu, lt0, 1);
        lt0 += __shfl_xor_sync(0xffffffffu, lt0, 2);
        lt1 += __shfl_xor_sync(0xffffffffu, lt1, 1);
        lt1 += __shfl_xor_sync(0xffffffffu, lt1, 2);

        l0 = l0 * c0 + lt0;  l1 = l1 * c1 + lt1;
        m0 = mn0;            m1 = mn1;

#pragma unroll
        for (int nf = 0; nf < 8; nf++) {
            o_acc[nf][0] *= c0; o_acc[nf][1] *= c0;
            o_acc[nf][2] *= c1; o_acc[nf][3] *= c1;
        }

#pragma unroll
        for (int ks = 0; ks < 4; ks++) {
            float p00 = sf[2 * ks][0],     p01 = sf[2 * ks][1];
            float p02 = sf[2 * ks][2],     p03 = sf[2 * ks][3];
            float p10 = sf[2 * ks + 1][0], p11 = sf[2 * ks + 1][1];
            float p12 = sf[2 * ks + 1][2], p13 = sf[2 * ks + 1][3];
            uint32_t ph[4], pl[4];
            ph[0] = pack2bf(p00, p01);
            ph[1] = pack2bf(p02, p03);
            ph[2] = pack2bf(p10, p11);
            ph[3] = pack2bf(p12, p13);
            pl[0] = pack2bf(p00 - bf_round(p00), p01 - bf_round(p01));
            pl[1] = pack2bf(p02 - bf_round(p02), p03 - bf_round(p03));
            pl[2] = pack2bf(p10 - bf_round(p10), p11 - bf_round(p11));
            pl[3] = pack2bf(p12 - bf_round(p12), p13 - bf_round(p13));
#pragma unroll
            for (int nf = 0; nf < 8; nf++) {
                uint32_t off = (uint32_t)(nf * 8 + brow) * AT_STRIDE_B
                             + (uint32_t)(ks * 16 + bcsel) * 2;
                uint32_t bh2[2], bl2[2];
                ldsm2(bh2, vb_hi + off);
                ldsm2(bl2, vb_lo + off);
                mma_bf16(o_acc[nf], ph, bh2);
                mma_bf16(o_acc[nf], pl, bh2);
                mma_bf16(o_acc[nf], ph, bl2);
            }
        }
    }

    const float inv0 = 1.f / l0, inv1 = 1.f / l1;
#pragma unroll
    for (int nf = 0; nf < 8; nf++) {
        int col = nf * 8 + (lane & 3) * 2;
        store_split2(Ohi, Olo, qk_base + (size_t)r0 * DMODEL + col,
                     o_acc[nf][0] * inv0, o_acc[nf][1] * inv0);
        store_split2(Ohi, Olo, qk_base + (size_t)(r0 + 8) * DMODEL + col,
                     o_acc[nf][2] * inv1, o_acc[nf][3] * inv1);
    }
}

// ---------------------------------------------------------------------------
// Launch
// ---------------------------------------------------------------------------
extern "C" void kernel_launch(void* const* d_in, const int* in_sizes, int n_in,
                              void* d_out, int out_size)
{
    const float* x  = (const float*)d_in[0];
    const float* Wq = (const float*)d_in[1];
    const float* Wk = (const float*)d_in[2];
    const float* Wv = (const float*)d_in[3];
    const float* Wo = (const float*)d_in[4];
    const int*   tp = (const int*)d_in[5];
    float* out = (float*)d_out;

    float* v;
    __nv_bfloat16 *ahi, *alo, *whi, *wlo, *qhi, *qlo, *khi, *klo, *vthi, *vtlo;
    float2* cs;
    cudaGetSymbolAddress((void**)&v,    g_v);
    cudaGetSymbolAddress((void**)&ahi,  g_ahi);
    cudaGetSymbolAddress((void**)&alo,  g_alo);
    cudaGetSymbolAddress((void**)&whi,  g_whi);
    cudaGetSymbolAddress((void**)&wlo,  g_wlo);
    cudaGetSymbolAddress((void**)&qhi,  g_qhi);
    cudaGetSymbolAddress((void**)&qlo,  g_qlo);
    cudaGetSymbolAddress((void**)&khi,  g_khi);
    cudaGetSymbolAddress((void**)&klo,  g_klo);
    cudaGetSymbolAddress((void**)&vthi, g_vthi);
    cudaGetSymbolAddress((void**)&vtlo, g_vtlo);
    cudaGetSymbolAddress((void**)&cs,   g_cs);

    cudaFuncSetAttribute(gemm_qkv, cudaFuncAttributeMaxDynamicSharedMemorySize, GEMM_SMEM);
    cudaFuncSetAttribute(gemm_out, cudaFuncAttributeMaxDynamicSharedMemorySize, GEMM_SMEM);
    cudaFuncSetAttribute(attn_mma, cudaFuncAttributeMaxDynamicSharedMemorySize, AT_SMEM);

    const int nx4 = MTOT * DMODEL / 4;
    const int nwAll = WSZ;

    split_bf16<<<(nx4 + 255) / 256, 256>>>(x, ahi, alo, nx4);
    split_w4<<<(nwAll + 255) / 256, 256>>>(Wq, Wk, Wv, Wo, whi, wlo);
    rope_table<<<(SEQ * 32 + 255) / 256, 256>>>(cs, tp);

    gemm_qkv<<<dim3(DMODEL / 128, MTOT / 128, 3), 256, GEMM_SMEM>>>(
        ahi, alo, whi, wlo, qhi, qlo, khi, klo, v, cs);

    vt_split<<<dim3(SEQ / 32, DK / 32, BATCH * NHEADS), dim3(32, 8)>>>(v, vthi, vtlo);

    attn_mma<<<dim3(SEQ / 128, NHEADS, BATCH), 256, AT_SMEM>>>(
        qhi, qlo, khi, klo, vthi, vtlo, ahi, alo);

    gemm_out<<<dim3(DMODEL / 128, MTOT / 128), 256, GEMM_SMEM>>>(
        ahi, alo, whi + (size_t)3 * WSZ, wlo + (size_t)3 * WSZ, out);
}

// round 8
// speedup vs baseline: 5.4680x; 1.0744x over previous
#include <cuda_runtime.h>
#include <cuda_bf16.h>
#include <math.h>
#include <stdint.h>

// ---------------------------------------------------------------------------
// Problem constants
// ---------------------------------------------------------------------------
#define BATCH   2
#define SEQ     2048
#define DMODEL  1024
#define NHEADS  16
#define DK      64
#define MTOT    (BATCH * SEQ)        // 4096
#define SCALE   0.125f               // 1/sqrt(64)
#define WSZ     (DMODEL * DMODEL)

// ---------------------------------------------------------------------------
// Scratch (__device__ globals; allocation-free rule)
// ---------------------------------------------------------------------------
__device__ float g_v[MTOT * DMODEL];
__device__ __nv_bfloat16 g_ahi[MTOT * DMODEL];
__device__ __nv_bfloat16 g_alo[MTOT * DMODEL];
__device__ __nv_bfloat16 g_whi[4 * WSZ];
__device__ __nv_bfloat16 g_wlo[4 * WSZ];
__device__ __nv_bfloat16 g_qhi[MTOT * DMODEL];
__device__ __nv_bfloat16 g_qlo[MTOT * DMODEL];
__device__ __nv_bfloat16 g_khi[MTOT * DMODEL];
__device__ __nv_bfloat16 g_klo[MTOT * DMODEL];
__device__ __nv_bfloat16 g_vthi[MTOT * DMODEL];
__device__ __nv_bfloat16 g_vtlo[MTOT * DMODEL];
__device__ float2 g_cs[SEQ * (DK / 2)];

// ---------------------------------------------------------------------------
// PTX helpers
// ---------------------------------------------------------------------------
__device__ __forceinline__ uint32_t smem_to_u32(const void* p) {
    uint32_t a;
    asm("{ .reg .u64 t; cvta.to.shared.u64 t, %1; cvt.u32.u64 %0, t; }"
        : "=r"(a) : "l"(p));
    return a;
}

__device__ __forceinline__ void cp_async16(uint32_t dst, const void* src) {
    asm volatile("cp.async.cg.shared.global [%0], [%1], 16;" :: "r"(dst), "l"(src));
}

__device__ __forceinline__ void ldsm4(uint32_t* r, uint32_t addr) {
    asm volatile("ldmatrix.sync.aligned.m8n8.x4.shared.b16 {%0,%1,%2,%3}, [%4];"
                 : "=r"(r[0]), "=r"(r[1]), "=r"(r[2]), "=r"(r[3]) : "r"(addr));
}

__device__ __forceinline__ void ldsm2(uint32_t* r, uint32_t addr) {
    asm volatile("ldmatrix.sync.aligned.m8n8.x2.shared.b16 {%0,%1}, [%2];"
                 : "=r"(r[0]), "=r"(r[1]) : "r"(addr));
}

__device__ __forceinline__ void mma_bf16(float* d, const uint32_t* a, const uint32_t* b) {
    asm volatile(
        "mma.sync.aligned.m16n8k16.row.col.f32.bf16.bf16.f32 "
        "{%0,%1,%2,%3}, {%4,%5,%6,%7}, {%8,%9}, {%0,%1,%2,%3};"
        : "+f"(d[0]), "+f"(d[1]), "+f"(d[2]), "+f"(d[3])
        : "r"(a[0]), "r"(a[1]), "r"(a[2]), "r"(a[3]), "r"(b[0]), "r"(b[1]));
}

__device__ __forceinline__ uint32_t pack2bf(float a, float b) {
    __nv_bfloat162 t = __floats2bfloat162_rn(a, b);
    return *reinterpret_cast<uint32_t*>(&t);
}
__device__ __forceinline__ float bf_round(float x) {
    return __bfloat162float(__float2bfloat16(x));
}
__device__ __forceinline__ void store_split2(
    __nv_bfloat16* hi, __nv_bfloat16* lo, size_t off, float a, float b)
{
    __nv_bfloat16 ha = __float2bfloat16(a), hb = __float2bfloat16(b);
    *(__nv_bfloat162*)(hi + off) = __nv_bfloat162(ha, hb);
    *(__nv_bfloat162*)(lo + off) = __nv_bfloat162(
        __float2bfloat16(a - __bfloat162float(ha)),
        __float2bfloat16(b - __bfloat162float(hb)));
}

// ---------------------------------------------------------------------------
// GEMM mainloop (NT, bf16x3, 128x128 tile, BK=32, 3-stage cp.async,
// SW64-swizzled unpadded 64B-row smem, B loaded via ldsm4 pairs).
// phys 16B-seg = seg ^ ((row>>1)&3)  -> conflict-free ldmatrix + stores.
// ---------------------------------------------------------------------------
#define MAT_B   8192u                // 128 rows * 64 B
#define STAGE_B 32768u               // Ahi|Alo|Bhi|Blo
#define GEMM_SMEM (3 * STAGE_B)      // 98304 B

__device__ __forceinline__ uint32_t sw64(int row, int seg) {
    return (uint32_t)(row * 64 + ((seg ^ ((row >> 1) & 3)) << 4));
}

__device__ __forceinline__ void gemm_issue(
    uint32_t dstHi, uint32_t dstLo,
    const __nv_bfloat16* srcHi, const __nv_bfloat16* srcLo, int t, int k0)
{
#pragma unroll
    for (int i = 0; i < 4; i++) {
        int chunk = t + (i << 7);
        int row = chunk >> 2, seg = chunk & 3;
        uint32_t so = sw64(row, seg);
        const size_t go = (size_t)row * DMODEL + k0 + seg * 8;
        cp_async16(dstHi + so, srcHi + go);
        cp_async16(dstLo + so, srcLo + go);
    }
    asm volatile("cp.async.commit_group;" ::: "memory");
}

__device__ __forceinline__ void gemm_mainloop(
    uint32_t sb, int tid, int wid, int lane,
    const __nv_bfloat16* __restrict__ Ahi, const __nv_bfloat16* __restrict__ Alo,
    const __nv_bfloat16* __restrict__ Bhi, const __nv_bfloat16* __restrict__ Blo,
    int bm, int bn, float acc[4][4][4])
{
    const bool isA = tid < 128;
    const int t = isA ? tid : tid - 128;
    const __nv_bfloat16* srcHi = isA ? (Ahi + (size_t)bm * DMODEL)
                                     : (Bhi + (size_t)bn * DMODEL);
    const __nv_bfloat16* srcLo = isA ? (Alo + (size_t)bm * DMODEL)
                                     : (Blo + (size_t)bn * DMODEL);
    const uint32_t matHiOff = isA ? 0u : 2u * MAT_B;
    const uint32_t matLoOff = matHiOff + MAT_B;

#pragma unroll
    for (int i = 0; i < 4; i++)
#pragma unroll
        for (int j = 0; j < 4; j++)
#pragma unroll
            for (int e = 0; e < 4; e++) acc[i][j][e] = 0.f;

    const int mwarp = wid & 1, nwarp = wid >> 1;

    // per-lane ldsm addressing (row component constant across chunks)
    const int arowb = mwarp * 64 + (lane & 7) + ((lane >> 3) & 1) * 8;
    const int asegb = (lane >> 4) & 1;               // +0 / +1 seg within ks
    // B pair rows: lanes 0-15 -> first 8 rows, lanes 16-31 -> +8 rows
    const int browb = nwarp * 32 + ((lane >> 4) & 1) * 8 + (lane & 7);
    const int bsegb = (lane >> 3) & 1;

    // prologue: stages 0,1
    gemm_issue(sb + matHiOff, sb + matLoOff, srcHi, srcLo, t, 0);
    gemm_issue(sb + STAGE_B + matHiOff, sb + STAGE_B + matLoOff, srcHi, srcLo, t, 32);

    for (int c = 0; c < 32; c++) {
        if (c < 31) asm volatile("cp.async.wait_group 1;" ::: "memory");
        else        asm volatile("cp.async.wait_group 0;" ::: "memory");
        __syncthreads();

        // issue stage c+2 early (buffer freed by the barrier above)
        if (c + 2 < 32) {
            const uint32_t base = sb + (uint32_t)((c + 2) % 3) * STAGE_B;
            gemm_issue(base + matHiOff, base + matLoOff, srcHi, srcLo, t, (c + 2) * 32);
        }

        const uint32_t stg = sb + (uint32_t)(c % 3) * STAGE_B;
        const uint32_t aHi = stg, aLo = stg + MAT_B;
        const uint32_t bHi = stg + 2u * MAT_B, bLo = stg + 3u * MAT_B;

#pragma unroll
        for (int ks = 0; ks < 2; ks++) {
            const int segA = ks * 2 + asegb;
            const int segB = ks * 2 + bsegb;

            uint32_t af[4][4], bh[2][4], bl[2][4];
#pragma unroll
            for (int mf = 0; mf < 4; mf++) {
                int row = arowb + mf * 16;
                ldsm4(af[mf], aHi + sw64(row, segA));
            }
#pragma unroll
            for (int p = 0; p < 2; p++) {
                int row = browb + p * 16;
                uint32_t off = sw64(row, segB);
                ldsm4(bh[p], bHi + off);
                ldsm4(bl[p], bLo + off);
            }
#pragma unroll
            for (int mf = 0; mf < 4; mf++)
#pragma unroll
                for (int p = 0; p < 2; p++) {
                    mma_bf16(acc[mf][2 * p],     af[mf], &bh[p][0]);
                    mma_bf16(acc[mf][2 * p + 1], af[mf], &bh[p][2]);
                }
#pragma unroll
            for (int mf = 0; mf < 4; mf++)
#pragma unroll
                for (int p = 0; p < 2; p++) {
                    mma_bf16(acc[mf][2 * p],     af[mf], &bl[p][0]);
                    mma_bf16(acc[mf][2 * p + 1], af[mf], &bl[p][2]);
                }
            // A-lo pass: load late (af dead) to cap register pressure
            uint32_t alf[4][4];
#pragma unroll
            for (int mf = 0; mf < 4; mf++) {
                int row = arowb + mf * 16;
                ldsm4(alf[mf], aLo + sw64(row, segA));
            }
#pragma unroll
            for (int mf = 0; mf < 4; mf++)
#pragma unroll
                for (int p = 0; p < 2; p++) {
                    mma_bf16(acc[mf][2 * p],     alf[mf], &bh[p][0]);
                    mma_bf16(acc[mf][2 * p + 1], alf[mf], &bh[p][2]);
                }
        }
        __syncthreads();
    }
}

// ---------------------------------------------------------------------------
// QKV GEMM (2 CTAs/SM): z=0 Q (rope+scale+split), z=1 K (rope+split), z=2 V.
// ---------------------------------------------------------------------------
__global__ __launch_bounds__(256, 2) void gemm_qkv(
    const __nv_bfloat16* __restrict__ Ahi, const __nv_bfloat16* __restrict__ Alo,
    const __nv_bfloat16* __restrict__ Whi, const __nv_bfloat16* __restrict__ Wlo,
    __nv_bfloat16* __restrict__ qhi, __nv_bfloat16* __restrict__ qlo,
    __nv_bfloat16* __restrict__ khi, __nv_bfloat16* __restrict__ klo,
    float* __restrict__ V, const float2* __restrict__ tab)
{
    extern __shared__ char smc[];
    const uint32_t sb = smem_to_u32(smc);
    const int tid = threadIdx.x, wid = tid >> 5, lane = tid & 31;
    const int bm = blockIdx.y * 128, bn = blockIdx.x * 128;
    const int z = blockIdx.z;

    float acc[4][4][4];
    gemm_mainloop(sb, tid, wid, lane, Ahi, Alo,
                  Whi + (size_t)z * WSZ, Wlo + (size_t)z * WSZ, bm, bn, acc);

    const int mwarp = wid & 1, nwarp = wid >> 1;
    const int rbase = bm + mwarp * 64 + (lane >> 2);
    const int cbase = bn + nwarp * 32 + (lane & 3) * 2;

    if (z == 2) {
#pragma unroll
        for (int mf = 0; mf < 4; mf++)
#pragma unroll
            for (int nf = 0; nf < 4; nf++) {
                size_t o0 = (size_t)(rbase + mf * 16) * DMODEL + cbase + nf * 8;
                *(float2*)&V[o0]              = make_float2(acc[mf][nf][0], acc[mf][nf][1]);
                *(float2*)&V[o0 + 8 * DMODEL] = make_float2(acc[mf][nf][2], acc[mf][nf][3]);
            }
        return;
    }

    const float sc = (z == 0) ? SCALE : 1.0f;
    __nv_bfloat16* hi = (z == 0) ? qhi : khi;
    __nv_bfloat16* lo = (z == 0) ? qlo : klo;
#pragma unroll
    for (int mf = 0; mf < 4; mf++)
#pragma unroll
        for (int nf = 0; nf < 4; nf++) {
            const int col = cbase + nf * 8;
            const int fi  = (col & 63) >> 1;
#pragma unroll
            for (int g = 0; g < 2; g++) {
                const int tok = rbase + mf * 16 + g * 8;
                const float2 cs = tab[((tok & (SEQ - 1)) << 5) + fi];
                float e = acc[mf][nf][2 * g], o = acc[mf][nf][2 * g + 1];
                float oe = (e * cs.x - o * cs.y) * sc;
                float oo = (o * cs.x + e * cs.y) * sc;
                store_split2(hi, lo, (size_t)tok * DMODEL + col, oe, oo);
            }
        }
}

// ---------------------------------------------------------------------------
// Output-projection GEMM (2 CTAs/SM): plain fp32 C.
// ---------------------------------------------------------------------------
__global__ __launch_bounds__(256, 2) void gemm_out(
    const __nv_bfloat16* __restrict__ Ahi, const __nv_bfloat16* __restrict__ Alo,
    const __nv_bfloat16* __restrict__ Bhi, const __nv_bfloat16* __restrict__ Blo,
    float* __restrict__ C)
{
    extern __shared__ char smc[];
    const uint32_t sb = smem_to_u32(smc);
    const int tid = threadIdx.x, wid = tid >> 5, lane = tid & 31;
    const int bm = blockIdx.y * 128, bn = blockIdx.x * 128;

    float acc[4][4][4];
    gemm_mainloop(sb, tid, wid, lane, Ahi, Alo, Bhi, Blo, bm, bn, acc);

    const int mwarp = wid & 1, nwarp = wid >> 1;
    const int rbase = bm + mwarp * 64 + (lane >> 2);
    const int cbase = bn + nwarp * 32 + (lane & 3) * 2;
#pragma unroll
    for (int mf = 0; mf < 4; mf++)
#pragma unroll
        for (int nf = 0; nf < 4; nf++) {
            size_t o0 = (size_t)(rbase + mf * 16) * DMODEL + cbase + nf * 8;
            *(float2*)&C[o0]              = make_float2(acc[mf][nf][0], acc[mf][nf][1]);
            *(float2*)&C[o0 + 8 * DMODEL] = make_float2(acc[mf][nf][2], acc[mf][nf][3]);
        }
}

// ---------------------------------------------------------------------------
// Splits
// ---------------------------------------------------------------------------
__global__ void split_bf16(const float* __restrict__ s,
                           __nv_bfloat16* __restrict__ hi,
                           __nv_bfloat16* __restrict__ lo, int n4)
{
    int i = blockIdx.x * blockDim.x + threadIdx.x;
    if (i >= n4) return;
    float4 v = ((const float4*)s)[i];
    __nv_bfloat16 h0 = __float2bfloat16(v.x), h1 = __float2bfloat16(v.y);
    __nv_bfloat16 h2 = __float2bfloat16(v.z), h3 = __float2bfloat16(v.w);
    ((__nv_bfloat162*)hi)[2 * i]     = __nv_bfloat162(h0, h1);
    ((__nv_bfloat162*)hi)[2 * i + 1] = __nv_bfloat162(h2, h3);
    ((__nv_bfloat162*)lo)[2 * i]     = __nv_bfloat162(
        __float2bfloat16(v.x - __bfloat162float(h0)),
        __float2bfloat16(v.y - __bfloat162float(h1)));
    ((__nv_bfloat162*)lo)[2 * i + 1] = __nv_bfloat162(
        __float2bfloat16(v.z - __bfloat162float(h2)),
        __float2bfloat16(v.w - __bfloat162float(h3)));
}

__global__ void split_w4(const float* __restrict__ w0, const float* __restrict__ w1,
                         const float* __restrict__ w2, const float* __restrict__ w3,
                         __nv_bfloat16* __restrict__ hi, __nv_bfloat16* __restrict__ lo)
{
    const int nw4 = WSZ / 4;
    int i = blockIdx.x * blockDim.x + threadIdx.x;
    if (i >= 4 * nw4) return;
    int z = i / nw4, r = i - z * nw4;
    const float* src = (z == 0) ? w0 : (z == 1) ? w1 : (z == 2) ? w2 : w3;
    float4 v = ((const float4*)src)[r];
    __nv_bfloat16* hz = hi + (size_t)z * WSZ;
    __nv_bfloat16* lz = lo + (size_t)z * WSZ;
    __nv_bfloat16 h0 = __float2bfloat16(v.x), h1 = __float2bfloat16(v.y);
    __nv_bfloat16 h2 = __float2bfloat16(v.z), h3 = __float2bfloat16(v.w);
    ((__nv_bfloat162*)hz)[2 * r]     = __nv_bfloat162(h0, h1);
    ((__nv_bfloat162*)hz)[2 * r + 1] = __nv_bfloat162(h2, h3);
    ((__nv_bfloat162*)lz)[2 * r]     = __nv_bfloat162(
        __float2bfloat16(v.x - __bfloat162float(h0)),
        __float2bfloat16(v.y - __bfloat162float(h1)));
    ((__nv_bfloat162*)lz)[2 * r + 1] = __nv_bfloat162(
        __float2bfloat16(v.z - __bfloat162float(h2)),
        __float2bfloat16(v.w - __bfloat162float(h3)));
}

// ---------------------------------------------------------------------------
// RoPE table
// ---------------------------------------------------------------------------
__global__ void rope_table(float2* __restrict__ tab, const int* __restrict__ pos)
{
    int i = blockIdx.x * blockDim.x + threadIdx.x;
    if (i >= SEQ * 32) return;
    int fi = i & 31, s = i >> 5;
    double invf = exp2(-(double)fi * 0.41524101186091903);
    float ang = (float)pos[s] * (float)invf;
    double sd, cd;
    sincos((double)ang, &sd, &cd);
    tab[i] = make_float2((float)cd, (float)sd);
}

// ---------------------------------------------------------------------------
// V transpose + split
// ---------------------------------------------------------------------------
__global__ void vt_split(const float* __restrict__ v,
                         __nv_bfloat16* __restrict__ vthi,
                         __nv_bfloat16* __restrict__ vtlo)
{
    __shared__ float t[32][33];
    const int bh = blockIdx.z, bb = bh >> 4, hh = bh & 15;
    const int s0 = blockIdx.x * 32, d0 = blockIdx.y * 32;
    const int tx = threadIdx.x, ty = threadIdx.y;

#pragma unroll
    for (int r = 0; r < 32; r += 8)
        t[ty + r][tx] = v[((size_t)bb * SEQ + s0 + ty + r) * DMODEL + hh * DK + d0 + tx];
    __syncthreads();
#pragma unroll
    for (int r = 0; r < 32; r += 8) {
        int d = d0 + ty + r;
        float val = t[tx][ty + r];
        size_t o = ((size_t)(bb * NHEADS + hh) * DK + d) * SEQ + s0 + tx;
        __nv_bfloat16 hv = __float2bfloat16(val);
        vthi[o] = hv;
        vtlo[o] = __float2bfloat16(val - __bfloat162float(hv));
    }
}

// ---------------------------------------------------------------------------
// Tensor-core causal flash attention (unchanged from R7).
// ---------------------------------------------------------------------------
#define AQ_MAT      18432u
#define AK_MAT      9216u
#define AT_STRIDE_B 144u
#define AT_SMEM     (2u * AQ_MAT + 8u * AK_MAT)

__device__ __forceinline__ void attn_issue_tile(
    uint32_t sb, int stage, int s0, int tid, size_t qk_base, size_t vt_base,
    const __nv_bfloat16* Khi, const __nv_bfloat16* Klo,
    const __nv_bfloat16* VThi, const __nv_bfloat16* VTlo)
{
    uint32_t base = sb + 2u * AQ_MAT + (uint32_t)stage * 4u * AK_MAT;
#pragma unroll
    for (int i = 0; i < 2; i++) {
        int c = tid + i * 256, row = c >> 3, seg = c & 7;
        uint32_t so = (uint32_t)row * AT_STRIDE_B + seg * 16;
        cp_async16(base + so,              Khi  + qk_base + (size_t)(s0 + row) * DMODEL + seg * 8);
        cp_async16(base + AK_MAT + so,     Klo  + qk_base + (size_t)(s0 + row) * DMODEL + seg * 8);
        cp_async16(base + 2 * AK_MAT + so, VThi + vt_base + (size_t)row * SEQ + s0 + seg * 8);
        cp_async16(base + 3 * AK_MAT + so, VTlo + vt_base + (size_t)row * SEQ + s0 + seg * 8);
    }
    asm volatile("cp.async.commit_group;" ::: "memory");
}

__global__ __launch_bounds__(256, 1) void attn_mma(
    const __nv_bfloat16* __restrict__ Qhi, const __nv_bfloat16* __restrict__ Qlo,
    const __nv_bfloat16* __restrict__ Khi, const __nv_bfloat16* __restrict__ Klo,
    const __nv_bfloat16* __restrict__ VThi, const __nv_bfloat16* __restrict__ VTlo,
    __nv_bfloat16* __restrict__ Ohi, __nv_bfloat16* __restrict__ Olo)
{
    extern __shared__ char smc[];
    const uint32_t sb = smem_to_u32(smc);
    const int tid = threadIdx.x, wid = tid >> 5, lane = tid & 31;
    const int b = blockIdx.z, h = blockIdx.y;
    const int q0 = (gridDim.x - 1 - blockIdx.x) * 128;

    const size_t qk_base = (size_t)b * SEQ * DMODEL + (size_t)h * DK;
    const size_t vt_base = ((size_t)(b * NHEADS + h)) * DK * SEQ;

#pragma unroll
    for (int i = 0; i < 4; i++) {
        int c = tid + i * 256, row = c >> 3, seg = c & 7;
        uint32_t so = (uint32_t)row * AT_STRIDE_B + seg * 16;
        cp_async16(sb + so,          Qhi + qk_base + (size_t)(q0 + row) * DMODEL + seg * 8);
        cp_async16(sb + AQ_MAT + so, Qlo + qk_base + (size_t)(q0 + row) * DMODEL + seg * 8);
    }
    asm volatile("cp.async.commit_group;" ::: "memory");
    asm volatile("cp.async.wait_group 0;" ::: "memory");
    __syncthreads();

    uint32_t qh[4][4], ql[4][4];
    {
        const int arow = wid * 16 + (lane & 7) + ((lane >> 3) & 1) * 8;
#pragma unroll
        for (int ks = 0; ks < 4; ks++) {
            uint32_t off = (uint32_t)arow * AT_STRIDE_B + (uint32_t)(ks * 16 + (lane >> 4) * 8) * 2;
            ldsm4(qh[ks], sb + off);
            ldsm4(ql[ks], sb + AQ_MAT + off);
        }
    }

    float o_acc[8][4];
#pragma unroll
    for (int nf = 0; nf < 8; nf++)
#pragma unroll
        for (int e = 0; e < 4; e++) o_acc[nf][e] = 0.f;
    float m0 = -INFINITY, m1 = -INFINITY, l0 = 0.f, l1 = 0.f;

    const int ktiles = (q0 >> 6) + 2;
    attn_issue_tile(sb, 0, 0, tid, qk_base, vt_base, Khi, Klo, VThi, VTlo);

    const int l16 = lane & 15;
    const int brow = l16 & 7;
    const int bcsel = ((l16 >> 3) & 1) * 8;
    const int r0 = q0 + wid * 16 + (lane >> 2);

    for (int kt = 0; kt < ktiles; kt++) {
        asm volatile("cp.async.wait_group 0;" ::: "memory");
        __syncthreads();
        if (kt + 1 < ktiles)
            attn_issue_tile(sb, (kt + 1) & 1, (kt + 1) * 64, tid, qk_base, vt_base,
                            Khi, Klo, VThi, VTlo);

        const uint32_t kb_hi = sb + 2u * AQ_MAT + (uint32_t)(kt & 1) * 4u * AK_MAT;
        const uint32_t kb_lo = kb_hi + AK_MAT;
        const uint32_t vb_hi = kb_hi + 2u * AK_MAT;
        const uint32_t vb_lo = kb_hi + 3u * AK_MAT;

        float sf[8][4];
#pragma unroll
        for (int nf = 0; nf < 8; nf++) {
            sf[nf][0] = sf[nf][1] = sf[nf][2] = sf[nf][3] = 0.f;
#pragma unroll
            for (int ks = 0; ks < 4; ks++) {
                uint32_t off = (uint32_t)(nf * 8 + brow) * AT_STRIDE_B
                             + (uint32_t)(ks * 16 + bcsel) * 2;
                uint32_t bh2[2], bl2[2];
                ldsm2(bh2, kb_hi + off);
                ldsm2(bl2, kb_lo + off);
                mma_bf16(sf[nf], qh[ks], bh2);
                mma_bf16(sf[nf], ql[ks], bh2);
                mma_bf16(sf[nf], qh[ks], bl2);
            }
        }

        if (kt >= ktiles - 2) {
            const int kc0 = kt * 64 + (lane & 3) * 2;
#pragma unroll
            for (int nf = 0; nf < 8; nf++) {
                int key = kc0 + nf * 8;
                if (key     > r0)     sf[nf][0] = -1e30f;
                if (key + 1 > r0)     sf[nf][1] = -1e30f;
                if (key     > r0 + 8) sf[nf][2] = -1e30f;
                if (key + 1 > r0 + 8) sf[nf][3] = -1e30f;
            }
        }

        float mt0 = sf[0][0], mt1 = sf[0][2];
#pragma unroll
        for (int nf = 0; nf < 8; nf++) {
            mt0 = fmaxf(mt0, fmaxf(sf[nf][0], sf[nf][1]));
            mt1 = fmaxf(mt1, fmaxf(sf[nf][2], sf[nf][3]));
        }
        mt0 = fmaxf(mt0, __shfl_xor_sync(0xffffffffu, mt0, 1));
        mt0 = fmaxf(mt0, __shfl_xor_sync(0xffffffffu, mt0, 2));
        mt1 = fmaxf(mt1, __shfl_xor_sync(0xffffffffu, mt1, 1));
        mt1 = fmaxf(mt1, __shfl_xor_sync(0xffffffffu, mt1, 2));

        float mn0 = fmaxf(m0, mt0), mn1 = fmaxf(m1, mt1);
        float c0 = __expf(m0 - mn0), c1 = __expf(m1 - mn1);

        float lt0 = 0.f, lt1 = 0.f;
#pragma unroll
        for (int nf = 0; nf < 8; nf++) {
            sf[nf][0] = __expf(sf[nf][0] - mn0);
            sf[nf][1] = __expf(sf[nf][1] - mn0);
            sf[nf][2] = __expf(sf[nf][2] - mn1);
            sf[nf][3] = __expf(sf[nf][3] - mn1);
            lt0 += sf[nf][0] + sf[nf][1];
            lt1 += sf[nf][2] + sf[nf][3];
        }
        lt0 += __shfl_xor_sync(0xffffffffu, lt0, 1);
        lt0 += __shfl_xor_sync(0xffffffffu, lt0, 2);
        lt1 += __shfl_xor_sync(0xffffffffu, lt1, 1);
        lt1 += __shfl_xor_sync(0xffffffffu, lt1, 2);

        l0 = l0 * c0 + lt0;  l1 = l1 * c1 + lt1;
        m0 = mn0;            m1 = mn1;

#pragma unroll
        for (int nf = 0; nf < 8; nf++) {
            o_acc[nf][0] *= c0; o_acc[nf][1] *= c0;
            o_acc[nf][2] *= c1; o_acc[nf][3] *= c1;
        }

#pragma unroll
        for (int ks = 0; ks < 4; ks++) {
            float p00 = sf[2 * ks][0],     p01 = sf[2 * ks][1];
            float p02 = sf[2 * ks][2],     p03 = sf[2 * ks][3];
            float p10 = sf[2 * ks + 1][0], p11 = sf[2 * ks + 1][1];
            float p12 = sf[2 * ks + 1][2], p13 = sf[2 * ks + 1][3];
            uint32_t ph[4], pl[4];
            ph[0] = pack2bf(p00, p01);
            ph[1] = pack2bf(p02, p03);
            ph[2] = pack2bf(p10, p11);
            ph[3] = pack2bf(p12, p13);
            pl[0] = pack2bf(p00 - bf_round(p00), p01 - bf_round(p01));
            pl[1] = pack2bf(p02 - bf_round(p02), p03 - bf_round(p03));
            pl[2] = pack2bf(p10 - bf_round(p10), p11 - bf_round(p11));
            pl[3] = pack2bf(p12 - bf_round(p12), p13 - bf_round(p13));
#pragma unroll
            for (int nf = 0; nf < 8; nf++) {
                uint32_t off = (uint32_t)(nf * 8 + brow) * AT_STRIDE_B
                             + (uint32_t)(ks * 16 + bcsel) * 2;
                uint32_t bh2[2], bl2[2];
                ldsm2(bh2, vb_hi + off);
                ldsm2(bl2, vb_lo + off);
                mma_bf16(o_acc[nf], ph, bh2);
                mma_bf16(o_acc[nf], pl, bh2);
                mma_bf16(o_acc[nf], ph, bl2);
            }
        }
    }

    const float inv0 = 1.f / l0, inv1 = 1.f / l1;
#pragma unroll
    for (int nf = 0; nf < 8; nf++) {
        int col = nf * 8 + (lane & 3) * 2;
        store_split2(Ohi, Olo, qk_base + (size_t)r0 * DMODEL + col,
                     o_acc[nf][0] * inv0, o_acc[nf][1] * inv0);
        store_split2(Ohi, Olo, qk_base + (size_t)(r0 + 8) * DMODEL + col,
                     o_acc[nf][2] * inv1, o_acc[nf][3] * inv1);
    }
}

// ---------------------------------------------------------------------------
// Launch
// ---------------------------------------------------------------------------
extern "C" void kernel_launch(void* const* d_in, const int* in_sizes, int n_in,
                              void* d_out, int out_size)
{
    const float* x  = (const float*)d_in[0];
    const float* Wq = (const float*)d_in[1];
    const float* Wk = (const float*)d_in[2];
    const float* Wv = (const float*)d_in[3];
    const float* Wo = (const float*)d_in[4];
    const int*   tp = (const int*)d_in[5];
    float* out = (float*)d_out;

    float* v;
    __nv_bfloat16 *ahi, *alo, *whi, *wlo, *qhi, *qlo, *khi, *klo, *vthi, *vtlo;
    float2* cs;
    cudaGetSymbolAddress((void**)&v,    g_v);
    cudaGetSymbolAddress((void**)&ahi,  g_ahi);
    cudaGetSymbolAddress((void**)&alo,  g_alo);
    cudaGetSymbolAddress((void**)&whi,  g_whi);
    cudaGetSymbolAddress((void**)&wlo,  g_wlo);
    cudaGetSymbolAddress((void**)&qhi,  g_qhi);
    cudaGetSymbolAddress((void**)&qlo,  g_qlo);
    cudaGetSymbolAddress((void**)&khi,  g_khi);
    cudaGetSymbolAddress((void**)&klo,  g_klo);
    cudaGetSymbolAddress((void**)&vthi, g_vthi);
    cudaGetSymbolAddress((void**)&vtlo, g_vtlo);
    cudaGetSymbolAddress((void**)&cs,   g_cs);

    cudaFuncSetAttribute(gemm_qkv, cudaFuncAttributeMaxDynamicSharedMemorySize, GEMM_SMEM);
    cudaFuncSetAttribute(gemm_out, cudaFuncAttributeMaxDynamicSharedMemorySize, GEMM_SMEM);
    cudaFuncSetAttribute(attn_mma, cudaFuncAttributeMaxDynamicSharedMemorySize, AT_SMEM);

    const int nx4 = MTOT * DMODEL / 4;
    const int nwAll = WSZ;

    split_bf16<<<(nx4 + 255) / 256, 256>>>(x, ahi, alo, nx4);
    split_w4<<<(nwAll + 255) / 256, 256>>>(Wq, Wk, Wv, Wo, whi, wlo);
    rope_table<<<(SEQ * 32 + 255) / 256, 256>>>(cs, tp);

    gemm_qkv<<<dim3(DMODEL / 128, MTOT / 128, 3), 256, GEMM_SMEM>>>(
        ahi, alo, whi, wlo, qhi, qlo, khi, klo, v, cs);

    vt_split<<<dim3(SEQ / 32, DK / 32, BATCH * NHEADS), dim3(32, 8)>>>(v, vthi, vtlo);

    attn_mma<<<dim3(SEQ / 128, NHEADS, BATCH), 256, AT_SMEM>>>(
        qhi, qlo, khi, klo, vthi, vtlo, ahi, alo);

    gemm_out<<<dim3(DMODEL / 128, MTOT / 128), 256, GEMM_SMEM>>>(
        ahi, alo, whi + (size_t)3 * WSZ, wlo + (size_t)3 * WSZ, out);
}